// round 1
// baseline (speedup 1.0000x reference)
#include <cuda_runtime.h>
#include <math.h>

#define B_   4
#define N_   1024
#define K_   512
#define H_   8
#define DH_  64
#define HID_ 2048
#define KG_  (3*K_)          // 1536
#define BN_  (B_*N_)         // 4096
#define BNK_ (B_*N_*K_)      // 2097152
#define BHN_ (B_*H_*N_)      // 32768
#define NN_  (N_*N_)         // 1048576

// ---------------- device scratch (static, no allocation) ----------------
__device__ float g_gcat[K_*KG_];
__device__ float g_w2q[K_*K_];
__device__ float g_w2k[K_*K_];
__device__ float g_ln1[BNK_];
__device__ float g_Z[BN_*KG_];
__device__ float g_a1[BNK_];
__device__ float g_mug[BNK_];
__device__ float g_q[BNK_];
__device__ float g_k[BNK_];
__device__ float g_v[BNK_];
__device__ float g_inv[BNK_];
__device__ float g_qinv[BNK_];
__device__ float g_skv[BNK_];
__device__ float g_e[BNK_];
__device__ float g_gam[BHN_];
__device__ float g_del[BHN_];
__device__ float g_beta[33554432];   // B*H*N*N
__device__ float g_bm[B_*NN_];
__device__ float g_attn[BNK_];
__device__ float g_o[BNK_];
__device__ float g_res[BNK_];
__device__ float g_ln2[BNK_];
__device__ float g_h[BNK_];
__device__ float g_hid[BN_*HID_];
__device__ float g_drive[BNK_];
__device__ float g_bh[BNK_];

// ---------------- reduction helpers ----------------
__device__ __forceinline__ float warpSum(float v) {
#pragma unroll
    for (int o = 16; o; o >>= 1) v += __shfl_down_sync(0xffffffffu, v, o);
    return v;
}
__device__ __forceinline__ float warpMax(float v) {
#pragma unroll
    for (int o = 16; o; o >>= 1) v = fmaxf(v, __shfl_down_sync(0xffffffffu, v, o));
    return v;
}

// ---------------- generic tiled GEMM: C = A(MxK) * B(KxN), row-major, batched ----------------
__global__ void gemm_kernel(const float* __restrict__ A, const float* __restrict__ Bm,
                            float* __restrict__ C,
                            int M, int N, int Kd, int lda, int ldb, int ldc,
                            long long sAo, long long sAi, long long sBo, long long sBi,
                            long long sCo, long long sCi, int innerDiv)
{
    int z = blockIdx.z;
    int zo = z / innerDiv, zi = z - zo * innerDiv;
    A  += zo * sAo + zi * sAi;
    Bm += zo * sBo + zi * sBi;
    C  += zo * sCo + zi * sCi;

    __shared__ float sA[16][65];
    __shared__ float sB[16][64];
    int tid = threadIdx.x;
    int tx = tid & 15, ty = tid >> 4;
    int row0 = blockIdx.y * 64, col0 = blockIdx.x * 64;
    float acc[4][4] = {};

    for (int k0 = 0; k0 < Kd; k0 += 16) {
#pragma unroll
        for (int e = tid; e < 1024; e += 256) {
            int m = e >> 4, kk = e & 15;
            float va = 0.f;
            if (row0 + m < M && k0 + kk < Kd)
                va = A[(long long)(row0 + m) * lda + k0 + kk];
            sA[kk][m] = va;
            int kb = e >> 6, n = e & 63;
            float vb = 0.f;
            if (k0 + kb < Kd && col0 + n < N)
                vb = Bm[(long long)(k0 + kb) * ldb + col0 + n];
            sB[kb][n] = vb;
        }
        __syncthreads();
#pragma unroll
        for (int kk = 0; kk < 16; kk++) {
            float a0 = sA[kk][ty*4+0], a1 = sA[kk][ty*4+1];
            float a2 = sA[kk][ty*4+2], a3 = sA[kk][ty*4+3];
            float b0 = sB[kk][tx*4+0], b1 = sB[kk][tx*4+1];
            float b2 = sB[kk][tx*4+2], b3 = sB[kk][tx*4+3];
            acc[0][0] += a0*b0; acc[0][1] += a0*b1; acc[0][2] += a0*b2; acc[0][3] += a0*b3;
            acc[1][0] += a1*b0; acc[1][1] += a1*b1; acc[1][2] += a1*b2; acc[1][3] += a1*b3;
            acc[2][0] += a2*b0; acc[2][1] += a2*b1; acc[2][2] += a2*b2; acc[2][3] += a2*b3;
            acc[3][0] += a3*b0; acc[3][1] += a3*b1; acc[3][2] += a3*b2; acc[3][3] += a3*b3;
        }
        __syncthreads();
    }
#pragma unroll
    for (int i = 0; i < 4; i++) {
        int r = row0 + ty * 4 + i;
        if (r >= M) continue;
#pragma unroll
        for (int j = 0; j < 4; j++) {
            int c = col0 + tx * 4 + j;
            if (c < N) C[(long long)r * ldc + c] = acc[i][j];
        }
    }
}

// ---------------- prep kernels ----------------
__global__ void prep_gcat_kernel(const float* __restrict__ gen)
{
    int t = blockIdx.x * 256 + threadIdx.x;
    if (t >= K_ * KG_) return;
    int l = t / KG_, c = t - l * KG_;
    int g = c >> 9, k = c & (K_ - 1);
    // Gcat[l][g*K + k] = generators[g][k][l]  so  Z = y @ Gcat gives Z[:,g*K+k] = (G_g y)_k
    g_gcat[t] = gen[((g * K_) + k) * K_ + l];
}

__global__ void prep_w2_kernel(const float* __restrict__ Wq, const float* __restrict__ Wk)
{
    int t = blockIdx.x * 256 + threadIdx.x;
    if (t >= K_ * K_) return;
    float a = Wq[t]; g_w2q[t] = a * a;
    float b = Wk[t]; g_w2k[t] = b * b;
}

// ---------------- layernorm ----------------
__global__ void ln_kernel(const float* __restrict__ x, const float* __restrict__ gw,
                          const float* __restrict__ bw, float* __restrict__ y)
{
    int bn = blockIdx.x;
    const float* xr = x + (long long)bn * K_;
    float* yr = y + (long long)bn * K_;
    int t = threadIdx.x;               // 256 threads, K=512
    float v0 = xr[t], v1 = xr[t + 256];
    __shared__ float red[8];
    __shared__ float s_mean, s_rstd;
    int lane = t & 31, w = t >> 5;
    float s = warpSum(v0 + v1);
    if (lane == 0) red[w] = s;
    __syncthreads();
    if (t == 0) {
        float tot = 0.f;
        for (int i = 0; i < 8; i++) tot += red[i];
        s_mean = tot * (1.f / 512.f);
    }
    __syncthreads();
    float m = s_mean;
    float d0 = v0 - m, d1 = v1 - m;
    float s2 = warpSum(d0 * d0 + d1 * d1);
    if (lane == 0) red[w] = s2;
    __syncthreads();
    if (t == 0) {
        float tot = 0.f;
        for (int i = 0; i < 8; i++) tot += red[i];
        s_rstd = rsqrtf(tot * (1.f / 512.f) + 1e-5f);
    }
    __syncthreads();
    float r = s_rstd;
    yr[t]       = d0 * r * gw[t]       + bw[t];
    yr[t + 256] = d1 * r * gw[t + 256] + bw[t + 256];
}

// ---------------- transport combines ----------------
__global__ void combine1_kernel(const float* __restrict__ phi, float sign)
{
    int i = blockIdx.x * 256 + threadIdx.x;
    if (i >= BNK_) return;
    int bn = i >> 9, k = i & (K_ - 1);
    const float* pp = phi + bn * 3;
    const float* z = g_Z + (long long)bn * KG_;
    g_a1[i] = sign * (pp[0] * z[k] + pp[1] * z[K_ + k] + pp[2] * z[2 * K_ + k]);
}

__global__ void combine2_kernel(const float* __restrict__ phi, float sign,
                                const float* __restrict__ xbase,
                                const float* __restrict__ resid,
                                float* __restrict__ outp)
{
    int i = blockIdx.x * 256 + threadIdx.x;
    if (i >= BNK_) return;
    int bn = i >> 9, k = i & (K_ - 1);
    const float* pp = phi + bn * 3;
    const float* z = g_Z + (long long)bn * KG_;
    float c = sign * (pp[0] * z[k] + pp[1] * z[K_ + k] + pp[2] * z[2 * K_ + k]);
    float r = xbase[i] + g_a1[i] + 0.5f * c;
    if (resid) r += resid[i];
    outp[i] = r;
}

// ---------------- attention prep ----------------
__global__ void prep_attn_kernel()
{
    int i = blockIdx.x * 256 + threadIdx.x;
    if (i >= BNK_) return;
    float sq = g_inv[i] + 1e-8f;      // g_inv currently holds raw sigma@Wq^2
    float inv = 1.f / sq;
    g_inv[i] = inv;
    g_qinv[i] = g_q[i] * inv;
    float sk = g_skv[i] + 1e-8f;      // raw sigma@Wk^2
    g_skv[i] = sk;
    float kv = g_k[i];
    g_e[i] = sk + kv * kv;
}

__global__ void gamdel_kernel()
{
    int bx = blockIdx.x;              // (b*H + h)*N + n
    int bh = bx >> 10;
    int n  = bx & (N_ - 1);
    int b = bh >> 3, h = bh & 7;
    int d = threadIdx.x;              // 64 threads
    long long base = ((long long)(b * N_ + n)) * K_ + h * DH_ + d;
    float q = g_q[base], inv = g_inv[base], skv = g_skv[base];
    float qq = q * q * inv;
    float lsq = -logf(inv);
    float lsk = logf(skv);
    qq = warpSum(qq); lsq = warpSum(lsq); lsk = warpSum(lsk);
    __shared__ float sh[3][2];
    int lane = d & 31, w = d >> 5;
    if (lane == 0) { sh[0][w] = qq; sh[1][w] = lsq; sh[2][w] = lsk; }
    __syncthreads();
    if (d == 0) {
        float QQ = sh[0][0] + sh[0][1];
        float LQ = sh[1][0] + sh[1][1];
        float LK = sh[2][0] + sh[2][1];
        g_gam[bx] = -0.5f * (QQ - (float)DH_ + LQ);   // per-row i constant (kappa = 1)
        g_del[bx] = 0.5f * LK;                        // per-col j constant
    }
}

// ---------------- KL score kernel: score = Qe.Ke + gam_i + del_j, causal mask ----------------
__global__ void score_kernel()
{
    int bh = blockIdx.z;              // b*H + h
    int b = bh >> 3, h = bh & 7;
    int i0 = blockIdx.y * 32, j0 = blockIdx.x * 32;
    int ti = threadIdx.y, tj = threadIdx.x;
    long long outBase = (((long long)bh * N_) + i0) * N_ + j0;
    if (j0 > i0 + 31) {               // fully masked tile
        g_beta[outBase + (long long)ti * N_ + tj] = -1e30f;
        return;
    }
    __shared__ float Qs[32][129];
    __shared__ float Ks[32][129];
    int tid = ti * 32 + tj;
    int hoff = h * DH_;
    for (int e = tid; e < 32 * 128; e += 1024) {
        int r = e >> 7, d = e & 127;
        long long qb = ((long long)(b * N_ + i0 + r)) * K_ + hoff;
        Qs[r][d] = (d < 64) ? (-0.5f) * g_inv[qb + d] : g_qinv[qb + d - 64];
        long long kb = ((long long)(b * N_ + j0 + r)) * K_ + hoff;
        Ks[r][d] = (d < 64) ? g_e[kb + d] : g_k[kb + d - 64];
    }
    __syncthreads();
    float s = 0.f;
#pragma unroll 8
    for (int d = 0; d < 128; d++) s += Qs[ti][d] * Ks[tj][d];
    int i = i0 + ti, j = j0 + tj;
    s += g_gam[bh * N_ + i] + g_del[bh * N_ + j];
    g_beta[outBase + (long long)ti * N_ + tj] = (j <= i) ? s : -1e30f;
}

// ---------------- row softmax over g_beta ----------------
__global__ void softmax_kernel()
{
    long long row = blockIdx.x;
    float* p = g_beta + row * N_;
    int t = threadIdx.x, lane = t & 31, w = t >> 5;
    __shared__ float red[8];
    __shared__ float s_m, s_s;
    float m = -1e30f;
    for (int j = t; j < N_; j += 256) m = fmaxf(m, p[j]);
    m = warpMax(m);
    if (lane == 0) red[w] = m;
    __syncthreads();
    if (t == 0) {
        float mm = red[0];
        for (int i = 1; i < 8; i++) mm = fmaxf(mm, red[i]);
        s_m = mm;
    }
    __syncthreads();
    m = s_m;
    float s = 0.f;
    for (int j = t; j < N_; j += 256) {
        float ev = expf(p[j] - m);
        p[j] = ev;
        s += ev;
    }
    s = warpSum(s);
    if (lane == 0) red[w] = s;
    __syncthreads();
    if (t == 0) {
        float tot = 0.f;
        for (int i = 0; i < 8; i++) tot += red[i];
        s_s = 1.f / tot;
    }
    __syncthreads();
    float inv = s_s;
    for (int j = t; j < N_; j += 256) p[j] *= inv;
}

// ---------------- beta_m = mean over heads ----------------
__global__ void bm_kernel()
{
    int t = blockIdx.x * 256 + threadIdx.x;
    if (t >= B_ * NN_) return;
    int b = t / NN_;
    int r = t - b * NN_;
    float s = 0.f;
#pragma unroll
    for (int h = 0; h < H_; h++)
        s += g_beta[((long long)(b * H_ + h)) * NN_ + r];
    g_bm[t] = s * 0.125f;
}

// ---------------- FFN pieces ----------------
__global__ void gelu_kernel(const float* __restrict__ bh1)
{
    int i = blockIdx.x * 256 + threadIdx.x;
    if (i >= BN_ * HID_) return;
    float x = g_hid[i] + bh1[i & (HID_ - 1)];
    float x3 = x * x * x;
    float tt = tanhf(0.7978845608028654f * (x + 0.044715f * x3));
    g_hid[i] = 0.5f * x * (1.f + tt);
}

__global__ void update_kernel(const float* __restrict__ hin, const float* __restrict__ mu_prior,
                              const float* __restrict__ bh2, const float* __restrict__ lr)
{
    int i = blockIdx.x * 256 + threadIdx.x;
    if (i >= BNK_) return;
    float h = hin[i];
    float drive = g_drive[i] + bh2[i & (K_ - 1)];
    float grad = 1e-3f * (h - mu_prior[i]) + (h - g_bh[i]);
    g_h[i] = h + lr[0] * (drive - grad);
}

__global__ void final_kernel(float* __restrict__ out)
{
    int i = blockIdx.x * 256 + threadIdx.x;
    if (i >= BNK_) return;
    out[i] = g_res[i] + g_h[i] - g_ln2[i];
}

// ---------------- host ----------------
static inline void launch_gemm(const float* A, const float* B, float* C,
                               int M, int N, int Kd, int lda, int ldb, int ldc,
                               long long sAo, long long sAi, long long sBo, long long sBi,
                               long long sCo, long long sCi, int innerDiv, int batch)
{
    dim3 g((N + 63) / 64, (M + 63) / 64, batch);
    gemm_kernel<<<g, 256>>>(A, B, C, M, N, Kd, lda, ldb, ldc,
                            sAo, sAi, sBo, sBi, sCo, sCi, innerDiv);
}

extern "C" void kernel_launch(void* const* d_in, const int* in_sizes, int n_in,
                              void* d_out, int out_size)
{
    const float* mu_q     = (const float*)d_in[0];
    const float* sigma_q  = (const float*)d_in[1];
    const float* phi      = (const float*)d_in[2];
    const float* gen      = (const float*)d_in[3];
    // d_in[4] = mask (causal tril) — computed analytically, not read
    const float* mu_prior = (const float*)d_in[5];
    const float* Wq  = (const float*)d_in[6];
    const float* Wk  = (const float*)d_in[7];
    const float* Wv  = (const float*)d_in[8];
    const float* Wo  = (const float*)d_in[9];
    const float* g1  = (const float*)d_in[10];
    const float* be1 = (const float*)d_in[11];
    const float* g2  = (const float*)d_in[12];
    const float* be2 = (const float*)d_in[13];
    const float* W1  = (const float*)d_in[14];
    const float* bh1 = (const float*)d_in[15];
    const float* W2  = (const float*)d_in[16];
    const float* bh2 = (const float*)d_in[17];
    const float* lr  = (const float*)d_in[18];

    void* tp;
#define GETSYM(var, sym) cudaGetSymbolAddress(&tp, sym); float* var = (float*)tp
    GETSYM(p_gcat, g_gcat);  GETSYM(p_w2q, g_w2q);  GETSYM(p_w2k, g_w2k);
    GETSYM(p_ln1, g_ln1);    GETSYM(p_Z, g_Z);      GETSYM(p_a1, g_a1);
    GETSYM(p_mug, g_mug);    GETSYM(p_q, g_q);      GETSYM(p_k, g_k);
    GETSYM(p_v, g_v);        GETSYM(p_inv, g_inv);  GETSYM(p_skv, g_skv);
    GETSYM(p_beta, g_beta);  GETSYM(p_bm, g_bm);    GETSYM(p_attn, g_attn);
    GETSYM(p_o, g_o);        GETSYM(p_res, g_res);  GETSYM(p_ln2, g_ln2);
    GETSYM(p_h, g_h);        GETSYM(p_hid, g_hid);  GETSYM(p_drive, g_drive);
    GETSYM(p_bh, g_bh);
#undef GETSYM

    const int EW = 256;
    const int GB_BNK = BNK_ / EW;

    // prep
    prep_gcat_kernel<<<(K_ * KG_ + EW - 1) / EW, EW>>>(gen);
    prep_w2_kernel<<<(K_ * K_ + EW - 1) / EW, EW>>>(Wq, Wk);

    // ---- attention sublayer ----
    ln_kernel<<<BN_, 256>>>(mu_q, g1, be1, p_ln1);

    // forward transport: mu_g = T(mu_n, +phi)
    launch_gemm(p_ln1, p_gcat, p_Z, BN_, KG_, K_, K_, KG_, KG_, 0,0,0,0,0,0, 1, 1);
    combine1_kernel<<<GB_BNK, EW>>>(phi, 1.f);
    launch_gemm(p_a1, p_gcat, p_Z, BN_, KG_, K_, K_, KG_, KG_, 0,0,0,0,0,0, 1, 1);
    combine2_kernel<<<GB_BNK, EW>>>(phi, 1.f, p_ln1, nullptr, p_mug);

    // projections
    launch_gemm(p_mug, Wq, p_q, BN_, K_, K_, K_, K_, K_, 0,0,0,0,0,0, 1, 1);
    launch_gemm(p_mug, Wk, p_k, BN_, K_, K_, K_, K_, K_, 0,0,0,0,0,0, 1, 1);
    launch_gemm(p_mug, Wv, p_v, BN_, K_, K_, K_, K_, K_, 0,0,0,0,0,0, 1, 1);
    launch_gemm(sigma_q, p_w2q, p_inv, BN_, K_, K_, K_, K_, K_, 0,0,0,0,0,0, 1, 1);  // raw sq
    launch_gemm(sigma_q, p_w2k, p_skv, BN_, K_, K_, K_, K_, K_, 0,0,0,0,0,0, 1, 1);  // raw sk

    prep_attn_kernel<<<GB_BNK, EW>>>();
    gamdel_kernel<<<BHN_, 64>>>();

    // KL scores + softmax
    score_kernel<<<dim3(N_ / 32, N_ / 32, B_ * H_), dim3(32, 32)>>>();
    softmax_kernel<<<BHN_, 256>>>();
    bm_kernel<<<(B_ * NN_ + EW - 1) / EW, EW>>>();

    // out = beta @ v  (batched over b,h; output directly in (B,N,K) layout)
    launch_gemm(p_beta, p_v, p_attn, N_, DH_, N_, N_, K_, K_,
                8LL * NN_, (long long)NN_,
                (long long)N_ * K_, 64,
                (long long)N_ * K_, 64, H_, B_ * H_);

    // out @ Wo, then back-transport with -phi, + residual mu_q -> mu_res
    launch_gemm(p_attn, Wo, p_o, BN_, K_, K_, K_, K_, K_, 0,0,0,0,0,0, 1, 1);
    launch_gemm(p_o, p_gcat, p_Z, BN_, KG_, K_, K_, KG_, KG_, 0,0,0,0,0,0, 1, 1);
    combine1_kernel<<<GB_BNK, EW>>>(phi, -1.f);
    launch_gemm(p_a1, p_gcat, p_Z, BN_, KG_, K_, K_, KG_, KG_, 0,0,0,0,0,0, 1, 1);
    combine2_kernel<<<GB_BNK, EW>>>(phi, -1.f, p_o, mu_q, p_res);

    // ---- FFN sublayer ----
    ln_kernel<<<BN_, 256>>>(p_res, g2, be2, p_ln2);

    const float* hin = p_ln2;
    for (int it = 0; it < 2; it++) {
        launch_gemm(hin, W1, p_hid, BN_, HID_, K_, K_, HID_, HID_, 0,0,0,0,0,0, 1, 1);
        gelu_kernel<<<(BN_ * HID_ + EW - 1) / EW, EW>>>(bh1);
        launch_gemm(p_hid, W2, p_drive, BN_, K_, HID_, HID_, K_, K_, 0,0,0,0,0,0, 1, 1);
        launch_gemm(p_bm, hin, p_bh, N_, K_, N_, N_, K_, K_,
                    (long long)NN_, 0, (long long)N_ * K_, 0, (long long)N_ * K_, 0, 1, B_);
        update_kernel<<<GB_BNK, EW>>>(hin, mu_prior, bh2, lr);
        hin = p_h;
    }

    // ---- outputs: (mu_out, sigma_q, phi) concatenated ----
    float* out = (float*)d_out;
    final_kernel<<<GB_BNK, EW>>>(out);
    cudaMemcpyAsync(out + BNK_, sigma_q, (size_t)BNK_ * sizeof(float),
                    cudaMemcpyDeviceToDevice);
    cudaMemcpyAsync(out + 2 * (size_t)BNK_, phi, (size_t)B_ * N_ * 3 * sizeof(float),
                    cudaMemcpyDeviceToDevice);
}

// round 2
// speedup vs baseline: 4.0908x; 4.0908x over previous
#include <cuda_runtime.h>
#include <math.h>

#define B_   4
#define N_   1024
#define K_   512
#define H_   8
#define DH_  64
#define HID_ 2048
#define KG_  (3*K_)          // 1536
#define BN_  (B_*N_)         // 4096
#define BNK_ (B_*N_*K_)      // 2097152
#define BHN_ (B_*H_*N_)      // 32768
#define NN_  (N_*N_)         // 1048576

// ---------------- device scratch (static, no allocation) ----------------
__device__ float g_gcat[K_*KG_];
__device__ float g_w2q[K_*K_];
__device__ float g_w2k[K_*K_];
__device__ float g_ln1[BNK_];
__device__ float g_Z[BN_*KG_];
__device__ float g_a1[BNK_];
__device__ float g_mug[BNK_];
__device__ float g_q[BNK_];
__device__ float g_k[BNK_];
__device__ float g_v[BNK_];
__device__ float g_inv[BNK_];
__device__ float g_qinv[BNK_];
__device__ float g_skv[BNK_];
__device__ float g_e[BNK_];
__device__ float g_gam[BHN_];
__device__ float g_del[BHN_];
__device__ float g_beta[33554432];   // B*H*N*N
__device__ float g_bm[B_*NN_];
__device__ float g_attn[BNK_];
__device__ float g_o[BNK_];
__device__ float g_res[BNK_];
__device__ float g_ln2[BNK_];
__device__ float g_h[BNK_];
__device__ float g_hid[BN_*HID_];
__device__ float g_drive[BNK_];
__device__ float g_bh[BNK_];

// ---------------- helpers ----------------
__device__ __forceinline__ float warpSum(float v) {
#pragma unroll
    for (int o = 16; o; o >>= 1) v += __shfl_down_sync(0xffffffffu, v, o);
    return v;
}
__device__ __forceinline__ float warpMax(float v) {
#pragma unroll
    for (int o = 16; o; o >>= 1) v = fmaxf(v, __shfl_down_sync(0xffffffffu, v, o));
    return v;
}
__device__ __forceinline__ unsigned f2tf(float x) {
    unsigned u;
    asm("cvt.rna.tf32.f32 %0, %1;" : "=r"(u) : "f"(x));
    return u;
}
__device__ __forceinline__ void cpa16(void* s, const void* g) {
    unsigned sa = (unsigned)__cvta_generic_to_shared(s);
    asm volatile("cp.async.cg.shared.global [%0], [%1], 16;" :: "r"(sa), "l"(g));
}

// ---------------- tf32 tensor-core GEMM: C = A(MxK) @ B(KxN), row-major, batched ----------------
// BM=128 fixed, BK=16, 256 threads = 8 warps (4 x 2), warp tile 32 x WN.
template<int BN, int WN, int NF>
__global__ __launch_bounds__(256, 2)
void gemm_tf32(const float* __restrict__ A, const float* __restrict__ Bm,
               float* __restrict__ C,
               int M, int N, int Kd, int lda, int ldb, int ldc,
               long long sAo, long long sAi, long long sBo, long long sBi,
               long long sCo, long long sCi, int innerDiv)
{
    constexpr int BM = 128;
    constexpr int BK = 16;
    constexpr int LDA = BK + 4;      // 20: conflict-free A fragment loads
    constexpr int LDB = BN + 8;      // 136/72: conflict-free B fragment loads
    __shared__ float sA[2][BM * LDA];
    __shared__ float sB[2][BK * LDB];

    int z = blockIdx.z;
    int zo = z / innerDiv, zi = z - zo * innerDiv;
    A  += zo * sAo + zi * sAi;
    Bm += zo * sBo + zi * sBi;
    C  += zo * sCo + zi * sCi;

    int tid = threadIdx.x;
    int wid = tid >> 5, lane = tid & 31;
    int wm = wid & 3, wn = wid >> 2;
    int row0 = blockIdx.y * BM, col0 = blockIdx.x * BN;
    int lr = lane >> 2, lc = lane & 3;

    float acc[2][NF][4];
#pragma unroll
    for (int mi = 0; mi < 2; mi++)
#pragma unroll
        for (int ni = 0; ni < NF; ni++)
#pragma unroll
            for (int r = 0; r < 4; r++) acc[mi][ni][r] = 0.f;

    int kTiles = Kd / BK;

    auto loadTile = [&](int t, int buf) {
        int k0 = t * BK;
#pragma unroll
        for (int c = tid; c < BM * 4; c += 256) {
            int m = c >> 2, k4 = (c & 3) * 4;
            cpa16(&sA[buf][m * LDA + k4],
                  A + (long long)(row0 + m) * lda + k0 + k4);
        }
#pragma unroll
        for (int c = tid; c < 4 * BN; c += 256) {
            int kk = c / (BN / 4), n4 = (c % (BN / 4)) * 4;
            cpa16(&sB[buf][kk * LDB + n4],
                  Bm + (long long)(k0 + kk) * ldb + col0 + n4);
        }
        asm volatile("cp.async.commit_group;");
    };

    loadTile(0, 0);
    for (int t = 0; t < kTiles; t++) {
        asm volatile("cp.async.wait_group 0;");
        __syncthreads();
        if (t + 1 < kTiles) loadTile(t + 1, (t + 1) & 1);
        int buf = t & 1;
#pragma unroll
        for (int ks = 0; ks < 2; ks++) {
            int kb = ks * 8 + lc;
            unsigned a[2][4];
#pragma unroll
            for (int mi = 0; mi < 2; mi++) {
                int r = wm * 32 + mi * 16 + lr;
                a[mi][0] = f2tf(sA[buf][r * LDA + kb]);
                a[mi][1] = f2tf(sA[buf][(r + 8) * LDA + kb]);
                a[mi][2] = f2tf(sA[buf][r * LDA + kb + 4]);
                a[mi][3] = f2tf(sA[buf][(r + 8) * LDA + kb + 4]);
            }
#pragma unroll
            for (int ni = 0; ni < NF; ni++) {
                int cc = wn * WN + ni * 8 + lr;
                unsigned b0 = f2tf(sB[buf][kb * LDB + cc]);
                unsigned b1 = f2tf(sB[buf][(kb + 4) * LDB + cc]);
#pragma unroll
                for (int mi = 0; mi < 2; mi++) {
                    asm volatile(
                        "mma.sync.aligned.m16n8k8.row.col.f32.tf32.tf32.f32 "
                        "{%0,%1,%2,%3}, {%4,%5,%6,%7}, {%8,%9}, {%0,%1,%2,%3};"
                        : "+f"(acc[mi][ni][0]), "+f"(acc[mi][ni][1]),
                          "+f"(acc[mi][ni][2]), "+f"(acc[mi][ni][3])
                        : "r"(a[mi][0]), "r"(a[mi][1]), "r"(a[mi][2]), "r"(a[mi][3]),
                          "r"(b0), "r"(b1));
                }
            }
        }
        __syncthreads();
    }

#pragma unroll
    for (int mi = 0; mi < 2; mi++) {
#pragma unroll
        for (int ni = 0; ni < NF; ni++) {
            int r = row0 + wm * 32 + mi * 16 + lr;
            int cc = col0 + wn * WN + ni * 8 + 2 * lc;
            float2 v0; v0.x = acc[mi][ni][0]; v0.y = acc[mi][ni][1];
            float2 v1; v1.x = acc[mi][ni][2]; v1.y = acc[mi][ni][3];
            *(float2*)&C[(long long)r * ldc + cc] = v0;
            *(float2*)&C[(long long)(r + 8) * ldc + cc] = v1;
        }
    }
}

// ---------------- prep kernels ----------------
__global__ void prep_gcat_kernel(const float* __restrict__ gen)
{
    int t = blockIdx.x * 256 + threadIdx.x;
    if (t >= K_ * KG_) return;
    int l = t / KG_, c = t - l * KG_;
    int g = c >> 9, k = c & (K_ - 1);
    g_gcat[t] = gen[((g * K_) + k) * K_ + l];
}

__global__ void prep_w2_kernel(const float* __restrict__ Wq, const float* __restrict__ Wk)
{
    int t = blockIdx.x * 256 + threadIdx.x;
    if (t >= K_ * K_) return;
    float a = Wq[t]; g_w2q[t] = a * a;
    float b = Wk[t]; g_w2k[t] = b * b;
}

// ---------------- layernorm ----------------
__global__ void ln_kernel(const float* __restrict__ x, const float* __restrict__ gw,
                          const float* __restrict__ bw, float* __restrict__ y)
{
    int bn = blockIdx.x;
    const float* xr = x + (long long)bn * K_;
    float* yr = y + (long long)bn * K_;
    int t = threadIdx.x;
    float v0 = xr[t], v1 = xr[t + 256];
    __shared__ float red[8];
    __shared__ float s_mean, s_rstd;
    int lane = t & 31, w = t >> 5;
    float s = warpSum(v0 + v1);
    if (lane == 0) red[w] = s;
    __syncthreads();
    if (t == 0) {
        float tot = 0.f;
        for (int i = 0; i < 8; i++) tot += red[i];
        s_mean = tot * (1.f / 512.f);
    }
    __syncthreads();
    float m = s_mean;
    float d0 = v0 - m, d1 = v1 - m;
    float s2 = warpSum(d0 * d0 + d1 * d1);
    if (lane == 0) red[w] = s2;
    __syncthreads();
    if (t == 0) {
        float tot = 0.f;
        for (int i = 0; i < 8; i++) tot += red[i];
        s_rstd = rsqrtf(tot * (1.f / 512.f) + 1e-5f);
    }
    __syncthreads();
    float r = s_rstd;
    yr[t]       = d0 * r * gw[t]       + bw[t];
    yr[t + 256] = d1 * r * gw[t + 256] + bw[t + 256];
}

// ---------------- transport combines ----------------
__global__ void combine1_kernel(const float* __restrict__ phi, float sign)
{
    int i = blockIdx.x * 256 + threadIdx.x;
    if (i >= BNK_) return;
    int bn = i >> 9, k = i & (K_ - 1);
    const float* pp = phi + bn * 3;
    const float* z = g_Z + (long long)bn * KG_;
    g_a1[i] = sign * (pp[0] * z[k] + pp[1] * z[K_ + k] + pp[2] * z[2 * K_ + k]);
}

__global__ void combine2_kernel(const float* __restrict__ phi, float sign,
                                const float* __restrict__ xbase,
                                const float* __restrict__ resid,
                                float* __restrict__ outp)
{
    int i = blockIdx.x * 256 + threadIdx.x;
    if (i >= BNK_) return;
    int bn = i >> 9, k = i & (K_ - 1);
    const float* pp = phi + bn * 3;
    const float* z = g_Z + (long long)bn * KG_;
    float c = sign * (pp[0] * z[k] + pp[1] * z[K_ + k] + pp[2] * z[2 * K_ + k]);
    float r = xbase[i] + g_a1[i] + 0.5f * c;
    if (resid) r += resid[i];
    outp[i] = r;
}

// ---------------- attention prep ----------------
__global__ void prep_attn_kernel()
{
    int i = blockIdx.x * 256 + threadIdx.x;
    if (i >= BNK_) return;
    float sq = g_inv[i] + 1e-8f;
    float inv = 1.f / sq;
    g_inv[i] = inv;
    g_qinv[i] = g_q[i] * inv;
    float sk = g_skv[i] + 1e-8f;
    g_skv[i] = sk;
    float kv = g_k[i];
    g_e[i] = sk + kv * kv;
}

__global__ void gamdel_kernel()
{
    int bx = blockIdx.x;
    int bh = bx >> 10;
    int n  = bx & (N_ - 1);
    int b = bh >> 3, h = bh & 7;
    int d = threadIdx.x;
    long long base = ((long long)(b * N_ + n)) * K_ + h * DH_ + d;
    float q = g_q[base], inv = g_inv[base], skv = g_skv[base];
    float qq = q * q * inv;
    float lsq = -logf(inv);
    float lsk = logf(skv);
    qq = warpSum(qq); lsq = warpSum(lsq); lsk = warpSum(lsk);
    __shared__ float sh[3][2];
    int lane = d & 31, w = d >> 5;
    if (lane == 0) { sh[0][w] = qq; sh[1][w] = lsq; sh[2][w] = lsk; }
    __syncthreads();
    if (d == 0) {
        float QQ = sh[0][0] + sh[0][1];
        float LQ = sh[1][0] + sh[1][1];
        float LK = sh[2][0] + sh[2][1];
        g_gam[bx] = -0.5f * (QQ - (float)DH_ + LQ);
        g_del[bx] = 0.5f * LK;
    }
}

// ---------------- KL score kernel: 64x64 tiles, 4x4 register blocking ----------------
__global__ void score_kernel()
{
    int bh = blockIdx.z;
    int b = bh >> 3, h = bh & 7;
    int i0 = blockIdx.y * 64, j0 = blockIdx.x * 64;
    int tid = threadIdx.x;
    int tx = tid & 15, ty = tid >> 4;
    long long outBase = ((long long)bh * N_ + i0) * N_ + j0;

    if (j0 > i0) {                    // fully masked tile
        float4 m4; m4.x = m4.y = m4.z = m4.w = -1e30f;
#pragma unroll
        for (int i = 0; i < 4; i++) {
            long long o = outBase + (long long)(ty * 4 + i) * N_ + tx * 4;
            *(float4*)(g_beta + o) = m4;
        }
        return;
    }

    __shared__ float Qs[64][33];
    __shared__ float Ks[64][33];
    float acc[4][4] = {};
    int hoff = h * DH_;

    for (int dc = 0; dc < 4; dc++) {
        int d0 = dc * 32;
        for (int e = tid; e < 2048; e += 256) {
            int r = e >> 5, d = e & 31;
            int dg = d0 + d;
            long long qb = ((long long)(b * N_ + i0 + r)) * K_ + hoff;
            long long kb = ((long long)(b * N_ + j0 + r)) * K_ + hoff;
            Qs[r][d] = (dg < 64) ? (-0.5f) * g_inv[qb + dg] : g_qinv[qb + dg - 64];
            Ks[r][d] = (dg < 64) ? g_e[kb + dg] : g_k[kb + dg - 64];
        }
        __syncthreads();
#pragma unroll
        for (int dd = 0; dd < 32; dd++) {
            float qr[4], kr[4];
#pragma unroll
            for (int i = 0; i < 4; i++) { qr[i] = Qs[ty * 4 + i][dd]; kr[i] = Ks[tx * 4 + i][dd]; }
#pragma unroll
            for (int i = 0; i < 4; i++)
#pragma unroll
                for (int j = 0; j < 4; j++) acc[i][j] += qr[i] * kr[j];
        }
        __syncthreads();
    }

#pragma unroll
    for (int i = 0; i < 4; i++) {
        int ii = i0 + ty * 4 + i;
        float gv = g_gam[bh * N_ + ii];
        int jb = j0 + tx * 4;
        float4 out;
        out.x = (jb     <= ii) ? acc[i][0] + gv + g_del[bh * N_ + jb]     : -1e30f;
        out.y = (jb + 1 <= ii) ? acc[i][1] + gv + g_del[bh * N_ + jb + 1] : -1e30f;
        out.z = (jb + 2 <= ii) ? acc[i][2] + gv + g_del[bh * N_ + jb + 2] : -1e30f;
        out.w = (jb + 3 <= ii) ? acc[i][3] + gv + g_del[bh * N_ + jb + 3] : -1e30f;
        *(float4*)(g_beta + outBase + (long long)(ty * 4 + i) * N_ + tx * 4) = out;
    }
}

// ---------------- row softmax over g_beta ----------------
__global__ void softmax_kernel()
{
    long long row = blockIdx.x;
    float* p = g_beta + row * N_;
    int t = threadIdx.x, lane = t & 31, w = t >> 5;
    __shared__ float red[8];
    __shared__ float s_m, s_s;
    float m = -1e30f;
    for (int j = t; j < N_; j += 256) m = fmaxf(m, p[j]);
    m = warpMax(m);
    if (lane == 0) red[w] = m;
    __syncthreads();
    if (t == 0) {
        float mm = red[0];
        for (int i = 1; i < 8; i++) mm = fmaxf(mm, red[i]);
        s_m = mm;
    }
    __syncthreads();
    m = s_m;
    float s = 0.f;
    for (int j = t; j < N_; j += 256) {
        float ev = expf(p[j] - m);
        p[j] = ev;
        s += ev;
    }
    s = warpSum(s);
    if (lane == 0) red[w] = s;
    __syncthreads();
    if (t == 0) {
        float tot = 0.f;
        for (int i = 0; i < 8; i++) tot += red[i];
        s_s = 1.f / tot;
    }
    __syncthreads();
    float inv = s_s;
    for (int j = t; j < N_; j += 256) p[j] *= inv;
}

// ---------------- beta_m = mean over heads (vectorized) ----------------
__global__ void bm_kernel()
{
    int t = blockIdx.x * 256 + threadIdx.x;
    if (t >= B_ * NN_ / 4) return;
    int b = t / (NN_ / 4);
    int r = t - b * (NN_ / 4);
    const float4* src = (const float4*)g_beta;
    float4 s; s.x = s.y = s.z = s.w = 0.f;
#pragma unroll
    for (int h = 0; h < H_; h++) {
        float4 v = src[((long long)(b * H_ + h)) * (NN_ / 4) + r];
        s.x += v.x; s.y += v.y; s.z += v.z; s.w += v.w;
    }
    s.x *= 0.125f; s.y *= 0.125f; s.z *= 0.125f; s.w *= 0.125f;
    ((float4*)g_bm)[t] = s;
}

// ---------------- FFN pieces ----------------
__global__ void gelu_kernel(const float* __restrict__ bh1)
{
    int i = blockIdx.x * 256 + threadIdx.x;
    if (i >= BN_ * HID_) return;
    float x = g_hid[i] + bh1[i & (HID_ - 1)];
    float x3 = x * x * x;
    float tt = tanhf(0.7978845608028654f * (x + 0.044715f * x3));
    g_hid[i] = 0.5f * x * (1.f + tt);
}

__global__ void update_kernel(const float* __restrict__ hin, const float* __restrict__ mu_prior,
                              const float* __restrict__ bh2, const float* __restrict__ lr)
{
    int i = blockIdx.x * 256 + threadIdx.x;
    if (i >= BNK_) return;
    float h = hin[i];
    float drive = g_drive[i] + bh2[i & (K_ - 1)];
    float grad = 1e-3f * (h - mu_prior[i]) + (h - g_bh[i]);
    g_h[i] = h + lr[0] * (drive - grad);
}

__global__ void final_kernel(float* __restrict__ out)
{
    int i = blockIdx.x * 256 + threadIdx.x;
    if (i >= BNK_) return;
    out[i] = g_res[i] + g_h[i] - g_ln2[i];
}

// ---------------- host ----------------
static inline void launch_gemm(const float* A, const float* B, float* C,
                               int M, int N, int Kd, int lda, int ldb, int ldc,
                               long long sAo, long long sAi, long long sBo, long long sBi,
                               long long sCo, long long sCi, int innerDiv, int batch)
{
    if (N % 128 == 0) {
        dim3 g(N / 128, M / 128, batch);
        gemm_tf32<128, 64, 8><<<g, 256>>>(A, B, C, M, N, Kd, lda, ldb, ldc,
                                          sAo, sAi, sBo, sBi, sCo, sCi, innerDiv);
    } else {
        dim3 g(N / 64, M / 128, batch);
        gemm_tf32<64, 32, 4><<<g, 256>>>(A, B, C, M, N, Kd, lda, ldb, ldc,
                                         sAo, sAi, sBo, sBi, sCo, sCi, innerDiv);
    }
}

extern "C" void kernel_launch(void* const* d_in, const int* in_sizes, int n_in,
                              void* d_out, int out_size)
{
    const float* mu_q     = (const float*)d_in[0];
    const float* sigma_q  = (const float*)d_in[1];
    const float* phi      = (const float*)d_in[2];
    const float* gen      = (const float*)d_in[3];
    const float* mu_prior = (const float*)d_in[5];
    const float* Wq  = (const float*)d_in[6];
    const float* Wk  = (const float*)d_in[7];
    const float* Wv  = (const float*)d_in[8];
    const float* Wo  = (const float*)d_in[9];
    const float* g1  = (const float*)d_in[10];
    const float* be1 = (const float*)d_in[11];
    const float* g2  = (const float*)d_in[12];
    const float* be2 = (const float*)d_in[13];
    const float* W1  = (const float*)d_in[14];
    const float* bh1 = (const float*)d_in[15];
    const float* W2  = (const float*)d_in[16];
    const float* bh2 = (const float*)d_in[17];
    const float* lr  = (const float*)d_in[18];

    void* tp;
#define GETSYM(var, sym) cudaGetSymbolAddress(&tp, sym); float* var = (float*)tp
    GETSYM(p_gcat, g_gcat);  GETSYM(p_w2q, g_w2q);  GETSYM(p_w2k, g_w2k);
    GETSYM(p_ln1, g_ln1);    GETSYM(p_Z, g_Z);      GETSYM(p_a1, g_a1);
    GETSYM(p_mug, g_mug);    GETSYM(p_q, g_q);      GETSYM(p_k, g_k);
    GETSYM(p_v, g_v);        GETSYM(p_inv, g_inv);  GETSYM(p_skv, g_skv);
    GETSYM(p_beta, g_beta);  GETSYM(p_bm, g_bm);    GETSYM(p_attn, g_attn);
    GETSYM(p_o, g_o);        GETSYM(p_res, g_res);  GETSYM(p_ln2, g_ln2);
    GETSYM(p_h, g_h);        GETSYM(p_hid, g_hid);  GETSYM(p_drive, g_drive);
    GETSYM(p_bh, g_bh);
#undef GETSYM

    const int EW = 256;
    const int GB_BNK = BNK_ / EW;

    prep_gcat_kernel<<<(K_ * KG_ + EW - 1) / EW, EW>>>(gen);
    prep_w2_kernel<<<(K_ * K_ + EW - 1) / EW, EW>>>(Wq, Wk);

    // ---- attention sublayer ----
    ln_kernel<<<BN_, 256>>>(mu_q, g1, be1, p_ln1);

    launch_gemm(p_ln1, p_gcat, p_Z, BN_, KG_, K_, K_, KG_, KG_, 0,0,0,0,0,0, 1, 1);
    combine1_kernel<<<GB_BNK, EW>>>(phi, 1.f);
    launch_gemm(p_a1, p_gcat, p_Z, BN_, KG_, K_, K_, KG_, KG_, 0,0,0,0,0,0, 1, 1);
    combine2_kernel<<<GB_BNK, EW>>>(phi, 1.f, p_ln1, nullptr, p_mug);

    launch_gemm(p_mug, Wq, p_q, BN_, K_, K_, K_, K_, K_, 0,0,0,0,0,0, 1, 1);
    launch_gemm(p_mug, Wk, p_k, BN_, K_, K_, K_, K_, K_, 0,0,0,0,0,0, 1, 1);
    launch_gemm(p_mug, Wv, p_v, BN_, K_, K_, K_, K_, K_, 0,0,0,0,0,0, 1, 1);
    launch_gemm(sigma_q, p_w2q, p_inv, BN_, K_, K_, K_, K_, K_, 0,0,0,0,0,0, 1, 1);
    launch_gemm(sigma_q, p_w2k, p_skv, BN_, K_, K_, K_, K_, K_, 0,0,0,0,0,0, 1, 1);

    prep_attn_kernel<<<GB_BNK, EW>>>();
    gamdel_kernel<<<BHN_, 64>>>();

    score_kernel<<<dim3(N_ / 64, N_ / 64, B_ * H_), 256>>>();
    softmax_kernel<<<BHN_, 256>>>();
    bm_kernel<<<(B_ * NN_ / 4 + EW - 1) / EW, EW>>>();

    // out = beta @ v  (batched over b,h)
    launch_gemm(p_beta, p_v, p_attn, N_, DH_, N_, N_, K_, K_,
                8LL * NN_, (long long)NN_,
                (long long)N_ * K_, 64,
                (long long)N_ * K_, 64, H_, B_ * H_);

    launch_gemm(p_attn, Wo, p_o, BN_, K_, K_, K_, K_, K_, 0,0,0,0,0,0, 1, 1);
    launch_gemm(p_o, p_gcat, p_Z, BN_, KG_, K_, K_, KG_, KG_, 0,0,0,0,0,0, 1, 1);
    combine1_kernel<<<GB_BNK, EW>>>(phi, -1.f);
    launch_gemm(p_a1, p_gcat, p_Z, BN_, KG_, K_, K_, KG_, KG_, 0,0,0,0,0,0, 1, 1);
    combine2_kernel<<<GB_BNK, EW>>>(phi, -1.f, p_o, mu_q, p_res);

    // ---- FFN sublayer ----
    ln_kernel<<<BN_, 256>>>(p_res, g2, be2, p_ln2);

    const float* hin = p_ln2;
    for (int it = 0; it < 2; it++) {
        launch_gemm(hin, W1, p_hid, BN_, HID_, K_, K_, HID_, HID_, 0,0,0,0,0,0, 1, 1);
        gelu_kernel<<<(BN_ * HID_ + EW - 1) / EW, EW>>>(bh1);
        launch_gemm(p_hid, W2, p_drive, BN_, K_, HID_, HID_, K_, K_, 0,0,0,0,0,0, 1, 1);
        launch_gemm(p_bm, hin, p_bh, N_, K_, N_, N_, K_, K_,
                    (long long)NN_, 0, (long long)N_ * K_, 0, (long long)N_ * K_, 0, 1, B_);
        update_kernel<<<GB_BNK, EW>>>(hin, mu_prior, bh2, lr);
        hin = p_h;
    }

    // ---- outputs: (mu_out, sigma_q, phi) ----
    float* out = (float*)d_out;
    final_kernel<<<GB_BNK, EW>>>(out);
    cudaMemcpyAsync(out + BNK_, sigma_q, (size_t)BNK_ * sizeof(float),
                    cudaMemcpyDeviceToDevice);
    cudaMemcpyAsync(out + 2 * (size_t)BNK_, phi, (size_t)B_ * N_ * 3 * sizeof(float),
                    cudaMemcpyDeviceToDevice);
}

// round 3
// speedup vs baseline: 4.8348x; 1.1819x over previous
#include <cuda_runtime.h>
#include <math.h>

#define B_   4
#define N_   1024
#define K_   512
#define H_   8
#define DH_  64
#define HID_ 2048
#define KG_  (3*K_)          // 1536
#define BN_  (B_*N_)         // 4096
#define BNK_ (B_*N_*K_)      // 2097152
#define BHN_ (B_*H_*N_)      // 32768
#define NN_  (N_*N_)         // 1048576
#define QKVW_ (3*K_)         // 1536 row width of qkv buffer

// ---------------- device scratch (static, no allocation) ----------------
__device__ float g_gcat[K_*KG_];
__device__ float g_wqkv[K_*QKVW_];
__device__ float g_w2qk[K_*2*K_];
__device__ float g_ln1[BNK_];
__device__ float g_Z[BN_*KG_];
__device__ float g_a1[BNK_];
__device__ float g_mug[BNK_];
__device__ float g_qkv[BN_*QKVW_];
__device__ float g_s2[BN_*2*K_];
__device__ float g_inv[BNK_];
__device__ float g_qinv[BNK_];
__device__ float g_skv[BNK_];
__device__ float g_e[BNK_];
__device__ float g_gam[BHN_];
__device__ float g_del[BHN_];
__device__ float g_beta[33554432];   // B*H*N*N
__device__ float g_bm[B_*NN_];
__device__ float g_attn[BNK_];
__device__ float g_o[BNK_];
__device__ float g_res[BNK_];
__device__ float g_ln2[BNK_];
__device__ float g_h[BNK_];
__device__ float g_hid[BN_*HID_];
__device__ float g_drive[BNK_];
__device__ float g_bh[BNK_];

// ---------------- helpers ----------------
__device__ __forceinline__ float warpSum(float v) {
#pragma unroll
    for (int o = 16; o; o >>= 1) v += __shfl_down_sync(0xffffffffu, v, o);
    return v;
}
__device__ __forceinline__ float warpMax(float v) {
#pragma unroll
    for (int o = 16; o; o >>= 1) v = fmaxf(v, __shfl_down_sync(0xffffffffu, v, o));
    return v;
}
__device__ __forceinline__ unsigned f2tf(float x) {
    unsigned u;
    asm("cvt.rna.tf32.f32 %0, %1;" : "=r"(u) : "f"(x));
    return u;
}
__device__ __forceinline__ void cpa16(void* s, const void* g) {
    unsigned sa = (unsigned)__cvta_generic_to_shared(s);
    asm volatile("cp.async.cg.shared.global [%0], [%1], 16;" :: "r"(sa), "l"(g));
}

// ---------------- tf32 tensor-core GEMM: C = A(MxK) @ B(KxN), row-major, batched ----------------
// BM=128 fixed, BK=16, 256 threads = 8 warps (4 x 2), warp tile 32 x WN.
// causal: limit K loop to k < row0 + BM (A's upper-triangle-of-row-tile is known zero).
template<int BN, int WN, int NF>
__global__ __launch_bounds__(256, 2)
void gemm_tf32(const float* __restrict__ A, const float* __restrict__ Bm,
               float* __restrict__ C,
               int M, int N, int Kd, int lda, int ldb, int ldc,
               long long sAo, long long sAi, long long sBo, long long sBi,
               long long sCo, long long sCi, int innerDiv, int causal)
{
    constexpr int BM = 128;
    constexpr int BK = 16;
    constexpr int LDA = BK + 4;      // 20
    constexpr int LDB = BN + 8;      // 136/72
    __shared__ float sA[2][BM * LDA];
    __shared__ float sB[2][BK * LDB];

    int z = blockIdx.z;
    int zo = z / innerDiv, zi = z - zo * innerDiv;
    A  += zo * sAo + zi * sAi;
    Bm += zo * sBo + zi * sBi;
    C  += zo * sCo + zi * sCi;

    int tid = threadIdx.x;
    int wid = tid >> 5, lane = tid & 31;
    int wm = wid & 3, wn = wid >> 2;
    int row0 = blockIdx.y * BM, col0 = blockIdx.x * BN;
    int lr = lane >> 2, lc = lane & 3;

    float acc[2][NF][4];
#pragma unroll
    for (int mi = 0; mi < 2; mi++)
#pragma unroll
        for (int ni = 0; ni < NF; ni++)
#pragma unroll
            for (int r = 0; r < 4; r++) acc[mi][ni][r] = 0.f;

    int kTiles = Kd / BK;
    if (causal) {
        int lim = (row0 + BM) / BK;
        if (lim < kTiles) kTiles = lim;
    }

    auto loadTile = [&](int t, int buf) {
        int k0 = t * BK;
#pragma unroll
        for (int c = tid; c < BM * 4; c += 256) {
            int m = c >> 2, k4 = (c & 3) * 4;
            cpa16(&sA[buf][m * LDA + k4],
                  A + (long long)(row0 + m) * lda + k0 + k4);
        }
#pragma unroll
        for (int c = tid; c < 4 * BN; c += 256) {
            int kk = c / (BN / 4), n4 = (c % (BN / 4)) * 4;
            cpa16(&sB[buf][kk * LDB + n4],
                  Bm + (long long)(k0 + kk) * ldb + col0 + n4);
        }
        asm volatile("cp.async.commit_group;");
    };

    loadTile(0, 0);
    for (int t = 0; t < kTiles; t++) {
        asm volatile("cp.async.wait_group 0;");
        __syncthreads();
        if (t + 1 < kTiles) loadTile(t + 1, (t + 1) & 1);
        int buf = t & 1;
#pragma unroll
        for (int ks = 0; ks < 2; ks++) {
            int kb = ks * 8 + lc;
            unsigned a[2][4];
#pragma unroll
            for (int mi = 0; mi < 2; mi++) {
                int r = wm * 32 + mi * 16 + lr;
                a[mi][0] = f2tf(sA[buf][r * LDA + kb]);
                a[mi][1] = f2tf(sA[buf][(r + 8) * LDA + kb]);
                a[mi][2] = f2tf(sA[buf][r * LDA + kb + 4]);
                a[mi][3] = f2tf(sA[buf][(r + 8) * LDA + kb + 4]);
            }
#pragma unroll
            for (int ni = 0; ni < NF; ni++) {
                int cc = wn * WN + ni * 8 + lr;
                unsigned b0 = f2tf(sB[buf][kb * LDB + cc]);
                unsigned b1 = f2tf(sB[buf][(kb + 4) * LDB + cc]);
#pragma unroll
                for (int mi = 0; mi < 2; mi++) {
                    asm volatile(
                        "mma.sync.aligned.m16n8k8.row.col.f32.tf32.tf32.f32 "
                        "{%0,%1,%2,%3}, {%4,%5,%6,%7}, {%8,%9}, {%0,%1,%2,%3};"
                        : "+f"(acc[mi][ni][0]), "+f"(acc[mi][ni][1]),
                          "+f"(acc[mi][ni][2]), "+f"(acc[mi][ni][3])
                        : "r"(a[mi][0]), "r"(a[mi][1]), "r"(a[mi][2]), "r"(a[mi][3]),
                          "r"(b0), "r"(b1));
                }
            }
        }
        __syncthreads();
    }

#pragma unroll
    for (int mi = 0; mi < 2; mi++) {
#pragma unroll
        for (int ni = 0; ni < NF; ni++) {
            int r = row0 + wm * 32 + mi * 16 + lr;
            int cc = col0 + wn * WN + ni * 8 + 2 * lc;
            float2 v0; v0.x = acc[mi][ni][0]; v0.y = acc[mi][ni][1];
            float2 v1; v1.x = acc[mi][ni][2]; v1.y = acc[mi][ni][3];
            *(float2*)&C[(long long)r * ldc + cc] = v0;
            *(float2*)&C[(long long)(r + 8) * ldc + cc] = v1;
        }
    }
}

// ---------------- prep kernels ----------------
__global__ void prep_gcat_kernel(const float* __restrict__ gen)
{
    int t = blockIdx.x * 256 + threadIdx.x;
    if (t >= K_ * KG_) return;
    int l = t / KG_, c = t - l * KG_;
    int g = c >> 9, k = c & (K_ - 1);
    g_gcat[t] = gen[((g * K_) + k) * K_ + l];
}

__global__ void prep_wqkv_kernel(const float* __restrict__ Wq, const float* __restrict__ Wk,
                                 const float* __restrict__ Wv)
{
    int t = blockIdx.x * 256 + threadIdx.x;
    if (t >= K_ * QKVW_) return;
    int l = t / QKVW_, c = t - l * QKVW_;
    int sel = c >> 9, cc = c & (K_ - 1);
    const float* W = (sel == 0) ? Wq : (sel == 1) ? Wk : Wv;
    g_wqkv[t] = W[l * K_ + cc];
}

__global__ void prep_w2qk_kernel(const float* __restrict__ Wq, const float* __restrict__ Wk)
{
    int t = blockIdx.x * 256 + threadIdx.x;
    if (t >= K_ * 2 * K_) return;
    int l = t / (2 * K_), c = t - l * 2 * K_;
    int sel = c >> 9, cc = c & (K_ - 1);
    float w = (sel == 0 ? Wq : Wk)[l * K_ + cc];
    g_w2qk[t] = w * w;
}

// ---------------- layernorm ----------------
__global__ void ln_kernel(const float* __restrict__ x, const float* __restrict__ gw,
                          const float* __restrict__ bw, float* __restrict__ y)
{
    int bn = blockIdx.x;
    const float* xr = x + (long long)bn * K_;
    float* yr = y + (long long)bn * K_;
    int t = threadIdx.x;
    float v0 = xr[t], v1 = xr[t + 256];
    __shared__ float red[8];
    __shared__ float s_mean, s_rstd;
    int lane = t & 31, w = t >> 5;
    float s = warpSum(v0 + v1);
    if (lane == 0) red[w] = s;
    __syncthreads();
    if (t == 0) {
        float tot = 0.f;
        for (int i = 0; i < 8; i++) tot += red[i];
        s_mean = tot * (1.f / 512.f);
    }
    __syncthreads();
    float m = s_mean;
    float d0 = v0 - m, d1 = v1 - m;
    float s2 = warpSum(d0 * d0 + d1 * d1);
    if (lane == 0) red[w] = s2;
    __syncthreads();
    if (t == 0) {
        float tot = 0.f;
        for (int i = 0; i < 8; i++) tot += red[i];
        s_rstd = rsqrtf(tot * (1.f / 512.f) + 1e-5f);
    }
    __syncthreads();
    float r = s_rstd;
    yr[t]       = d0 * r * gw[t]       + bw[t];
    yr[t + 256] = d1 * r * gw[t + 256] + bw[t + 256];
}

// ---------------- transport combines ----------------
__global__ void combine1_kernel(const float* __restrict__ phi, float sign)
{
    int i = blockIdx.x * 256 + threadIdx.x;
    if (i >= BNK_) return;
    int bn = i >> 9, k = i & (K_ - 1);
    const float* pp = phi + bn * 3;
    const float* z = g_Z + (long long)bn * KG_;
    g_a1[i] = sign * (pp[0] * z[k] + pp[1] * z[K_ + k] + pp[2] * z[2 * K_ + k]);
}

__global__ void combine2_kernel(const float* __restrict__ phi, float sign,
                                const float* __restrict__ xbase,
                                const float* __restrict__ resid,
                                float* __restrict__ outp)
{
    int i = blockIdx.x * 256 + threadIdx.x;
    if (i >= BNK_) return;
    int bn = i >> 9, k = i & (K_ - 1);
    const float* pp = phi + bn * 3;
    const float* z = g_Z + (long long)bn * KG_;
    float c = sign * (pp[0] * z[k] + pp[1] * z[K_ + k] + pp[2] * z[2 * K_ + k]);
    float r = xbase[i] + g_a1[i] + 0.5f * c;
    if (resid) r += resid[i];
    outp[i] = r;
}

// ---------------- attention prep ----------------
__global__ void prep_attn_kernel()
{
    int i = blockIdx.x * 256 + threadIdx.x;
    if (i >= BNK_) return;
    int bn = i >> 9, k = i & (K_ - 1);
    float sqraw = g_s2[(long long)bn * (2 * K_) + k];
    float inv = 1.f / (sqraw + 1e-8f);
    float q = g_qkv[(long long)bn * QKVW_ + k];
    g_inv[i] = inv;
    g_qinv[i] = q * inv;
    float sk = g_s2[(long long)bn * (2 * K_) + K_ + k] + 1e-8f;
    g_skv[i] = sk;
    float kv = g_qkv[(long long)bn * QKVW_ + K_ + k];
    g_e[i] = sk + kv * kv;
}

__global__ void gamdel_kernel()
{
    int bx = blockIdx.x;
    int bh = bx >> 10;
    int n  = bx & (N_ - 1);
    int b = bh >> 3, h = bh & 7;
    int d = threadIdx.x;
    long long rowq = ((long long)(b * N_ + n)) * QKVW_ + h * DH_ + d;
    long long rowi = ((long long)(b * N_ + n)) * K_ + h * DH_ + d;
    float q = g_qkv[rowq], inv = g_inv[rowi], skv = g_skv[rowi];
    float qq = q * q * inv;
    float lsq = -logf(inv);
    float lsk = logf(skv);
    qq = warpSum(qq); lsq = warpSum(lsq); lsk = warpSum(lsk);
    __shared__ float sh[3][2];
    int lane = d & 31, w = d >> 5;
    if (lane == 0) { sh[0][w] = qq; sh[1][w] = lsq; sh[2][w] = lsk; }
    __syncthreads();
    if (d == 0) {
        float QQ = sh[0][0] + sh[0][1];
        float LQ = sh[1][0] + sh[1][1];
        float LK = sh[2][0] + sh[2][1];
        g_gam[bx] = -0.5f * (QQ - (float)DH_ + LQ);
        g_del[bx] = 0.5f * LK;
    }
}

// ---------------- KL score kernel: tf32 mma, 64x64 tiles, 2 x 64-deep K chunks ----------------
__global__ __launch_bounds__(256) void score_kernel()
{
    int bh = blockIdx.z;
    int b = bh >> 3, h = bh & 7;
    int i0 = blockIdx.y * 64, j0 = blockIdx.x * 64;
    if (j0 > i0) return;               // fully masked tile: never read downstream

    constexpr int LDK = 68;
    __shared__ float Qs[64 * LDK];
    __shared__ float Ks[64 * LDK];
    int tid = threadIdx.x;
    int wid = tid >> 5, lane = tid & 31;
    int wm = wid & 3, wn = wid >> 2;   // 4 x 2 warps, warp tile 16 x 32
    int lr = lane >> 2, lc = lane & 3;
    int hoff = h * DH_;

    float acc[4][4] = {};

#pragma unroll
    for (int dc = 0; dc < 2; dc++) {
        for (int e = tid; e < 64 * 16; e += 256) {
            int r = e >> 4, c4 = (e & 15) * 4;
            long long qrow = (long long)(b * N_ + i0 + r);
            long long krow = (long long)(b * N_ + j0 + r);
            float4 qv, kv;
            if (dc == 0) {
                qv = *(const float4*)&g_inv[qrow * K_ + hoff + c4];
                qv.x *= -0.5f; qv.y *= -0.5f; qv.z *= -0.5f; qv.w *= -0.5f;
                kv = *(const float4*)&g_e[krow * K_ + hoff + c4];
            } else {
                qv = *(const float4*)&g_qinv[qrow * K_ + hoff + c4];
                kv = *(const float4*)&g_qkv[krow * QKVW_ + K_ + hoff + c4];
            }
            *(float4*)&Qs[r * LDK + c4] = qv;
            *(float4*)&Ks[r * LDK + c4] = kv;
        }
        __syncthreads();
#pragma unroll
        for (int ks = 0; ks < 8; ks++) {
            int kb = ks * 8 + lc;
            int ar = wm * 16 + lr;
            unsigned a0 = f2tf(Qs[ar * LDK + kb]);
            unsigned a1 = f2tf(Qs[(ar + 8) * LDK + kb]);
            unsigned a2 = f2tf(Qs[ar * LDK + kb + 4]);
            unsigned a3 = f2tf(Qs[(ar + 8) * LDK + kb + 4]);
#pragma unroll
            for (int ni = 0; ni < 4; ni++) {
                int bc = wn * 32 + ni * 8 + lr;
                unsigned b0 = f2tf(Ks[bc * LDK + kb]);
                unsigned b1 = f2tf(Ks[bc * LDK + kb + 4]);
                asm volatile(
                    "mma.sync.aligned.m16n8k8.row.col.f32.tf32.tf32.f32 "
                    "{%0,%1,%2,%3}, {%4,%5,%6,%7}, {%8,%9}, {%0,%1,%2,%3};"
                    : "+f"(acc[ni][0]), "+f"(acc[ni][1]),
                      "+f"(acc[ni][2]), "+f"(acc[ni][3])
                    : "r"(a0), "r"(a1), "r"(a2), "r"(a3), "r"(b0), "r"(b1));
            }
        }
        __syncthreads();
    }

    long long gdb = (long long)bh * N_;
#pragma unroll
    for (int half = 0; half < 2; half++) {
        int i = i0 + wm * 16 + lr + half * 8;
        float gv = g_gam[gdb + i];
#pragma unroll
        for (int ni = 0; ni < 4; ni++) {
            int j = j0 + wn * 32 + ni * 8 + 2 * lc;
            float2 o;
            o.x = acc[ni][half * 2 + 0] + gv + g_del[gdb + j];
            o.y = acc[ni][half * 2 + 1] + gv + g_del[gdb + j + 1];
            *(float2*)&g_beta[(gdb + i) * N_ + j] = o;
        }
    }
}

// ---------------- fused softmax (8 heads) + beta_m head-mean, causal-truncated ----------------
__global__ __launch_bounds__(256) void softmax_bm_kernel()
{
    int bi = blockIdx.x;               // b*N + i
    int b = bi >> 10, i = bi & (N_ - 1);
    int Jmax = ((i >> 7) + 1) << 7;    // beta@v / bm@h read columns < Jmax (128-row tiles)
    int t = threadIdx.x;
    int lane = t & 31, w = t >> 5;
    __shared__ float red[8];
    __shared__ float s_val;
    float bmacc[4] = {0.f, 0.f, 0.f, 0.f};

    for (int h = 0; h < H_; h++) {
        float* p = g_beta + (((long long)(b * H_ + h)) * N_ + i) * N_;
        float ev[4];
        float m = -1e30f;
#pragma unroll
        for (int jj = 0; jj < 4; jj++) {
            int j = t + jj * 256;
            ev[jj] = (j <= i) ? p[j] : -1e30f;
            m = fmaxf(m, ev[jj]);
        }
        m = warpMax(m);
        if (lane == 0) red[w] = m;
        __syncthreads();
        if (t == 0) {
            float mm = red[0];
            for (int x = 1; x < 8; x++) mm = fmaxf(mm, red[x]);
            s_val = mm;
        }
        __syncthreads();
        m = s_val;
        float s = 0.f;
#pragma unroll
        for (int jj = 0; jj < 4; jj++) {
            ev[jj] = (t + jj * 256 <= i) ? expf(ev[jj] - m) : 0.f;
            s += ev[jj];
        }
        s = warpSum(s);
        if (lane == 0) red[w] = s;
        __syncthreads();
        if (t == 0) {
            float tot = 0.f;
            for (int x = 0; x < 8; x++) tot += red[x];
            s_val = 1.f / tot;
        }
        __syncthreads();
        float inv = s_val;
#pragma unroll
        for (int jj = 0; jj < 4; jj++) {
            int j = t + jj * 256;
            float v = ev[jj] * inv;
            if (j < Jmax) p[j] = v;    // zeros for i < j < Jmax
            bmacc[jj] += v;
        }
        __syncthreads();
    }

    float* bm = g_bm + ((long long)b * N_ + i) * N_;
#pragma unroll
    for (int jj = 0; jj < 4; jj++) {
        int j = t + jj * 256;
        if (j < Jmax) bm[j] = bmacc[jj] * 0.125f;
    }
}

// ---------------- FFN pieces ----------------
__global__ void gelu_kernel(const float* __restrict__ bh1)
{
    int i = blockIdx.x * 256 + threadIdx.x;
    if (i >= BN_ * HID_) return;
    float x = g_hid[i] + bh1[i & (HID_ - 1)];
    float x3 = x * x * x;
    float tt = tanhf(0.7978845608028654f * (x + 0.044715f * x3));
    g_hid[i] = 0.5f * x * (1.f + tt);
}

__global__ void update_kernel(const float* __restrict__ hin, const float* __restrict__ mu_prior,
                              const float* __restrict__ bh2, const float* __restrict__ lr)
{
    int i = blockIdx.x * 256 + threadIdx.x;
    if (i >= BNK_) return;
    float h = hin[i];
    float drive = g_drive[i] + bh2[i & (K_ - 1)];
    float grad = 1e-3f * (h - mu_prior[i]) + (h - g_bh[i]);
    g_h[i] = h + lr[0] * (drive - grad);
}

__global__ void final_kernel(float* __restrict__ out)
{
    int i = blockIdx.x * 256 + threadIdx.x;
    if (i >= BNK_) return;
    out[i] = g_res[i] + g_h[i] - g_ln2[i];
}

// ---------------- host ----------------
static inline void launch_gemm(const float* A, const float* B, float* C,
                               int M, int N, int Kd, int lda, int ldb, int ldc,
                               long long sAo, long long sAi, long long sBo, long long sBi,
                               long long sCo, long long sCi, int innerDiv, int batch,
                               int causal = 0)
{
    if (N % 128 == 0) {
        dim3 g(N / 128, M / 128, batch);
        gemm_tf32<128, 64, 8><<<g, 256>>>(A, B, C, M, N, Kd, lda, ldb, ldc,
                                          sAo, sAi, sBo, sBi, sCo, sCi, innerDiv, causal);
    } else {
        dim3 g(N / 64, M / 128, batch);
        gemm_tf32<64, 32, 4><<<g, 256>>>(A, B, C, M, N, Kd, lda, ldb, ldc,
                                         sAo, sAi, sBo, sBi, sCo, sCi, innerDiv, causal);
    }
}

extern "C" void kernel_launch(void* const* d_in, const int* in_sizes, int n_in,
                              void* d_out, int out_size)
{
    const float* mu_q     = (const float*)d_in[0];
    const float* sigma_q  = (const float*)d_in[1];
    const float* phi      = (const float*)d_in[2];
    const float* gen      = (const float*)d_in[3];
    const float* mu_prior = (const float*)d_in[5];
    const float* Wq  = (const float*)d_in[6];
    const float* Wk  = (const float*)d_in[7];
    const float* Wv  = (const float*)d_in[8];
    const float* Wo  = (const float*)d_in[9];
    const float* g1  = (const float*)d_in[10];
    const float* be1 = (const float*)d_in[11];
    const float* g2  = (const float*)d_in[12];
    const float* be2 = (const float*)d_in[13];
    const float* W1  = (const float*)d_in[14];
    const float* bh1 = (const float*)d_in[15];
    const float* W2  = (const float*)d_in[16];
    const float* bh2 = (const float*)d_in[17];
    const float* lr  = (const float*)d_in[18];

    void* tp;
#define GETSYM(var, sym) cudaGetSymbolAddress(&tp, sym); float* var = (float*)tp
    GETSYM(p_gcat, g_gcat);  GETSYM(p_wqkv, g_wqkv); GETSYM(p_w2qk, g_w2qk);
    GETSYM(p_ln1, g_ln1);    GETSYM(p_Z, g_Z);       GETSYM(p_a1, g_a1);
    GETSYM(p_mug, g_mug);    GETSYM(p_qkv, g_qkv);   GETSYM(p_s2, g_s2);
    GETSYM(p_beta, g_beta);  GETSYM(p_bm, g_bm);     GETSYM(p_attn, g_attn);
    GETSYM(p_o, g_o);        GETSYM(p_res, g_res);   GETSYM(p_ln2, g_ln2);
    GETSYM(p_h, g_h);        GETSYM(p_hid, g_hid);   GETSYM(p_drive, g_drive);
    GETSYM(p_bh, g_bh);
#undef GETSYM

    const int EW = 256;
    const int GB_BNK = BNK_ / EW;

    prep_gcat_kernel<<<(K_ * KG_ + EW - 1) / EW, EW>>>(gen);
    prep_wqkv_kernel<<<(K_ * QKVW_ + EW - 1) / EW, EW>>>(Wq, Wk, Wv);
    prep_w2qk_kernel<<<(K_ * 2 * K_ + EW - 1) / EW, EW>>>(Wq, Wk);

    // ---- attention sublayer ----
    ln_kernel<<<BN_, 256>>>(mu_q, g1, be1, p_ln1);

    launch_gemm(p_ln1, p_gcat, p_Z, BN_, KG_, K_, K_, KG_, KG_, 0,0,0,0,0,0, 1, 1);
    combine1_kernel<<<GB_BNK, EW>>>(phi, 1.f);
    launch_gemm(p_a1, p_gcat, p_Z, BN_, KG_, K_, K_, KG_, KG_, 0,0,0,0,0,0, 1, 1);
    combine2_kernel<<<GB_BNK, EW>>>(phi, 1.f, p_ln1, nullptr, p_mug);

    // fused QKV projection and variance projections
    launch_gemm(p_mug, p_wqkv, p_qkv, BN_, QKVW_, K_, K_, QKVW_, QKVW_, 0,0,0,0,0,0, 1, 1);
    launch_gemm(sigma_q, p_w2qk, p_s2, BN_, 2 * K_, K_, K_, 2 * K_, 2 * K_, 0,0,0,0,0,0, 1, 1);

    prep_attn_kernel<<<GB_BNK, EW>>>();
    gamdel_kernel<<<BHN_, 64>>>();

    score_kernel<<<dim3(N_ / 64, N_ / 64, B_ * H_), 256>>>();
    softmax_bm_kernel<<<BN_, 256>>>();

    // out = beta @ v  (batched over b,h), causal K-truncation
    launch_gemm(p_beta, p_qkv + 2 * K_, p_attn, N_, DH_, N_, N_, QKVW_, K_,
                8LL * NN_, (long long)NN_,
                (long long)N_ * QKVW_, 64,
                (long long)N_ * K_, 64, H_, B_ * H_, 1);

    launch_gemm(p_attn, Wo, p_o, BN_, K_, K_, K_, K_, K_, 0,0,0,0,0,0, 1, 1);
    launch_gemm(p_o, p_gcat, p_Z, BN_, KG_, K_, K_, KG_, KG_, 0,0,0,0,0,0, 1, 1);
    combine1_kernel<<<GB_BNK, EW>>>(phi, -1.f);
    launch_gemm(p_a1, p_gcat, p_Z, BN_, KG_, K_, K_, KG_, KG_, 0,0,0,0,0,0, 1, 1);
    combine2_kernel<<<GB_BNK, EW>>>(phi, -1.f, p_o, mu_q, p_res);

    // ---- FFN sublayer ----
    ln_kernel<<<BN_, 256>>>(p_res, g2, be2, p_ln2);

    const float* hin = p_ln2;
    for (int it = 0; it < 2; it++) {
        launch_gemm(hin, W1, p_hid, BN_, HID_, K_, K_, HID_, HID_, 0,0,0,0,0,0, 1, 1);
        gelu_kernel<<<(BN_ * HID_ + EW - 1) / EW, EW>>>(bh1);
        launch_gemm(p_hid, W2, p_drive, BN_, K_, HID_, HID_, K_, K_, 0,0,0,0,0,0, 1, 1);
        launch_gemm(p_bm, hin, p_bh, N_, K_, N_, N_, K_, K_,
                    (long long)NN_, 0, (long long)N_ * K_, 0, (long long)N_ * K_, 0,
                    1, B_, 1);
        update_kernel<<<GB_BNK, EW>>>(hin, mu_prior, bh2, lr);
        hin = p_h;
    }

    // ---- outputs: (mu_out, sigma_q, phi) ----
    float* out = (float*)d_out;
    final_kernel<<<GB_BNK, EW>>>(out);
    cudaMemcpyAsync(out + BNK_, sigma_q, (size_t)BNK_ * sizeof(float),
                    cudaMemcpyDeviceToDevice);
    cudaMemcpyAsync(out + 2 * (size_t)BNK_, phi, (size_t)B_ * N_ * 3 * sizeof(float),
                    cudaMemcpyDeviceToDevice);
}

// round 4
// speedup vs baseline: 4.9529x; 1.0244x over previous
#include <cuda_runtime.h>
#include <math.h>

#define B_   4
#define N_   1024
#define K_   512
#define H_   8
#define DH_  64
#define HID_ 2048
#define KG_  (3*K_)          // 1536
#define BN_  (B_*N_)         // 4096
#define BNK_ (B_*N_*K_)      // 2097152
#define BHN_ (B_*H_*N_)      // 32768
#define NN_  (N_*N_)         // 1048576
#define QKVW_ (3*K_)         // 1536

// ---------------- device scratch (static, no allocation) ----------------
__device__ float g_gcat[K_*KG_];
__device__ float g_wqkv[K_*QKVW_];
__device__ float g_w2qk[K_*2*K_];
__device__ float g_ln1[BNK_];
__device__ float g_Z[BN_*KG_];
__device__ float g_a1[BNK_];
__device__ float g_mug[BNK_];
__device__ float g_qkv[BN_*QKVW_];
__device__ float g_s2[BN_*2*K_];
__device__ float g_inv[BNK_];
__device__ float g_qinv[BNK_];
__device__ float g_e[BNK_];
__device__ float g_gam[BHN_];
__device__ float g_del[BHN_];
__device__ float g_beta[33554432];   // B*H*N*N
__device__ float g_bm[B_*NN_];
__device__ float g_attn[BNK_];
__device__ float g_o[BNK_];
__device__ float g_res[BNK_];
__device__ float g_ln2[BNK_];
__device__ float g_h[BNK_];
__device__ float g_hid[BN_*HID_];
__device__ float g_bh[BNK_];

// ---------------- helpers ----------------
__device__ __forceinline__ float warpSum(float v) {
#pragma unroll
    for (int o = 16; o; o >>= 1) v += __shfl_down_sync(0xffffffffu, v, o);
    return v;
}
__device__ __forceinline__ float warpMax(float v) {
#pragma unroll
    for (int o = 16; o; o >>= 1) v = fmaxf(v, __shfl_down_sync(0xffffffffu, v, o));
    return v;
}
__device__ __forceinline__ unsigned f2tf(float x) {
    unsigned u;
    asm("cvt.rna.tf32.f32 %0, %1;" : "=r"(u) : "f"(x));
    return u;
}
__device__ __forceinline__ void cpa16(void* s, const void* g) {
    unsigned sa = (unsigned)__cvta_generic_to_shared(s);
    asm volatile("cp.async.cg.shared.global [%0], [%1], 16;" :: "r"(sa), "l"(g));
}

// ---------------- tf32 tensor-core GEMM, 3-stage cp.async, fused epilogues --------------
// BM=128, BK=16, 256 threads = 8 warps (4 x 2), warp tile 32 x WN.
// epi: 0 none; 1 gelu(acc+bias); 2 VFE update; 3 VFE update + final residual.
template<int BN, int WN, int NF>
__global__ __launch_bounds__(256, 2)
void gemm_tf32(const float* __restrict__ A, const float* __restrict__ Bm,
               float* __restrict__ C,
               int M, int N, int Kd, int lda, int ldb, int ldc,
               long long sAo, long long sAi, long long sBo, long long sBi,
               long long sCo, long long sCi, int innerDiv, int causal,
               int epi,
               const float* __restrict__ bias,
               const float* __restrict__ e_hin,  const float* __restrict__ e_prior,
               const float* __restrict__ e_aux,  const float* __restrict__ e_lr,
               const float* __restrict__ e_res,  const float* __restrict__ e_ln2)
{
    constexpr int BM = 128;
    constexpr int BK = 16;
    constexpr int LDA = BK + 4;      // 20
    constexpr int LDB = BN + 8;      // 136/72
    extern __shared__ float dsm[];
    float* sA = dsm;                         // 3 * BM*LDA
    float* sB = dsm + 3 * BM * LDA;          // 3 * BK*LDB

    int z = blockIdx.z;
    int zo = z / innerDiv, zi = z - zo * innerDiv;
    A  += zo * sAo + zi * sAi;
    Bm += zo * sBo + zi * sBi;
    C  += zo * sCo + zi * sCi;

    int tid = threadIdx.x;
    int wid = tid >> 5, lane = tid & 31;
    int wm = wid & 3, wn = wid >> 2;
    int row0 = blockIdx.y * BM, col0 = blockIdx.x * BN;
    int lr = lane >> 2, lc = lane & 3;

    float acc[2][NF][4];
#pragma unroll
    for (int mi = 0; mi < 2; mi++)
#pragma unroll
        for (int ni = 0; ni < NF; ni++)
#pragma unroll
            for (int r = 0; r < 4; r++) acc[mi][ni][r] = 0.f;

    int kTiles = Kd / BK;
    if (causal) {
        int lim = (row0 + BM) / BK;
        if (lim < kTiles) kTiles = lim;
    }

    auto loadTile = [&](int t, int buf) {
        int k0 = t * BK;
        float* pA = sA + buf * BM * LDA;
        float* pB = sB + buf * BK * LDB;
#pragma unroll
        for (int c = tid; c < BM * 4; c += 256) {
            int m = c >> 2, k4 = (c & 3) * 4;
            cpa16(&pA[m * LDA + k4],
                  A + (long long)(row0 + m) * lda + k0 + k4);
        }
#pragma unroll
        for (int c = tid; c < 4 * BN; c += 256) {
            int kk = c / (BN / 4), n4 = (c % (BN / 4)) * 4;
            cpa16(&pB[kk * LDB + n4],
                  Bm + (long long)(k0 + kk) * ldb + col0 + n4);
        }
        asm volatile("cp.async.commit_group;");
    };

    loadTile(0, 0);
    loadTile(1, 1);
    for (int t = 0; t < kTiles; t++) {
        asm volatile("cp.async.wait_group 1;");
        __syncthreads();
        if (t + 2 < kTiles) loadTile(t + 2, (t + 2) % 3);
        else asm volatile("cp.async.commit_group;");
        int buf = t % 3;
        const float* pA = sA + buf * BM * LDA;
        const float* pB = sB + buf * BK * LDB;
#pragma unroll
        for (int ks = 0; ks < 2; ks++) {
            int kb = ks * 8 + lc;
            unsigned a[2][4];
#pragma unroll
            for (int mi = 0; mi < 2; mi++) {
                int r = wm * 32 + mi * 16 + lr;
                a[mi][0] = f2tf(pA[r * LDA + kb]);
                a[mi][1] = f2tf(pA[(r + 8) * LDA + kb]);
                a[mi][2] = f2tf(pA[r * LDA + kb + 4]);
                a[mi][3] = f2tf(pA[(r + 8) * LDA + kb + 4]);
            }
#pragma unroll
            for (int ni = 0; ni < NF; ni++) {
                int cc = wn * WN + ni * 8 + lr;
                unsigned b0 = f2tf(pB[kb * LDB + cc]);
                unsigned b1 = f2tf(pB[(kb + 4) * LDB + cc]);
#pragma unroll
                for (int mi = 0; mi < 2; mi++) {
                    asm volatile(
                        "mma.sync.aligned.m16n8k8.row.col.f32.tf32.tf32.f32 "
                        "{%0,%1,%2,%3}, {%4,%5,%6,%7}, {%8,%9}, {%0,%1,%2,%3};"
                        : "+f"(acc[mi][ni][0]), "+f"(acc[mi][ni][1]),
                          "+f"(acc[mi][ni][2]), "+f"(acc[mi][ni][3])
                        : "r"(a[mi][0]), "r"(a[mi][1]), "r"(a[mi][2]), "r"(a[mi][3]),
                          "r"(b0), "r"(b1));
                }
            }
        }
    }

    auto epival = [&](float a, int r, int c) -> float {
        if (epi == 0) return a;
        float x = a + bias[c];
        if (epi == 1) {
            float x3 = x * x * x;
            return 0.5f * x * (1.f + tanhf(0.7978845608028654f * (x + 0.044715f * x3)));
        }
        long long off = (long long)r * ldc + c;
        float hv = e_hin[off];
        float val = hv + e_lr[0] * (x - (1e-3f * (hv - e_prior[off]) + (hv - e_aux[off])));
        if (epi == 3) val = e_res[off] + val - e_ln2[off];
        return val;
    };

#pragma unroll
    for (int mi = 0; mi < 2; mi++) {
#pragma unroll
        for (int ni = 0; ni < NF; ni++) {
            int r = row0 + wm * 32 + mi * 16 + lr;
            int cc = col0 + wn * WN + ni * 8 + 2 * lc;
            float2 v0, v1;
            v0.x = epival(acc[mi][ni][0], r, cc);
            v0.y = epival(acc[mi][ni][1], r, cc + 1);
            v1.x = epival(acc[mi][ni][2], r + 8, cc);
            v1.y = epival(acc[mi][ni][3], r + 8, cc + 1);
            *(float2*)&C[(long long)r * ldc + cc] = v0;
            *(float2*)&C[(long long)(r + 8) * ldc + cc] = v1;
        }
    }
}

// ---------------- prep kernels ----------------
__global__ void prep_gcat_kernel(const float* __restrict__ gen)
{
    int t = blockIdx.x * 256 + threadIdx.x;
    if (t >= K_ * KG_) return;
    int l = t / KG_, c = t - l * KG_;
    int g = c >> 9, k = c & (K_ - 1);
    g_gcat[t] = gen[((g * K_) + k) * K_ + l];
}

__global__ void prep_wqkv_kernel(const float* __restrict__ Wq, const float* __restrict__ Wk,
                                 const float* __restrict__ Wv)
{
    int t = blockIdx.x * 256 + threadIdx.x;
    if (t >= K_ * QKVW_) return;
    int l = t / QKVW_, c = t - l * QKVW_;
    int sel = c >> 9, cc = c & (K_ - 1);
    const float* W = (sel == 0) ? Wq : (sel == 1) ? Wk : Wv;
    g_wqkv[t] = W[l * K_ + cc];
}

__global__ void prep_w2qk_kernel(const float* __restrict__ Wq, const float* __restrict__ Wk)
{
    int t = blockIdx.x * 256 + threadIdx.x;
    if (t >= K_ * 2 * K_) return;
    int l = t / (2 * K_), c = t - l * 2 * K_;
    int sel = c >> 9, cc = c & (K_ - 1);
    float w = (sel == 0 ? Wq : Wk)[l * K_ + cc];
    g_w2qk[t] = w * w;
}

// ---------------- layernorm ----------------
__global__ void ln_kernel(const float* __restrict__ x, const float* __restrict__ gw,
                          const float* __restrict__ bw, float* __restrict__ y)
{
    int bn = blockIdx.x;
    const float* xr = x + (long long)bn * K_;
    float* yr = y + (long long)bn * K_;
    int t = threadIdx.x;
    float v0 = xr[t], v1 = xr[t + 256];
    __shared__ float red[8];
    __shared__ float s_mean, s_rstd;
    int lane = t & 31, w = t >> 5;
    float s = warpSum(v0 + v1);
    if (lane == 0) red[w] = s;
    __syncthreads();
    if (t == 0) {
        float tot = 0.f;
        for (int i = 0; i < 8; i++) tot += red[i];
        s_mean = tot * (1.f / 512.f);
    }
    __syncthreads();
    float m = s_mean;
    float d0 = v0 - m, d1 = v1 - m;
    float s2 = warpSum(d0 * d0 + d1 * d1);
    if (lane == 0) red[w] = s2;
    __syncthreads();
    if (t == 0) {
        float tot = 0.f;
        for (int i = 0; i < 8; i++) tot += red[i];
        s_rstd = rsqrtf(tot * (1.f / 512.f) + 1e-5f);
    }
    __syncthreads();
    float r = s_rstd;
    yr[t]       = d0 * r * gw[t]       + bw[t];
    yr[t + 256] = d1 * r * gw[t + 256] + bw[t + 256];
}

// ---------------- transport combines ----------------
__global__ void combine1_kernel(const float* __restrict__ phi, float sign)
{
    int i = blockIdx.x * 256 + threadIdx.x;
    if (i >= BNK_) return;
    int bn = i >> 9, k = i & (K_ - 1);
    const float* pp = phi + bn * 3;
    const float* z = g_Z + (long long)bn * KG_;
    g_a1[i] = sign * (pp[0] * z[k] + pp[1] * z[K_ + k] + pp[2] * z[2 * K_ + k]);
}

__global__ void combine2_kernel(const float* __restrict__ phi, float sign,
                                const float* __restrict__ xbase,
                                const float* __restrict__ resid,
                                float* __restrict__ outp)
{
    int i = blockIdx.x * 256 + threadIdx.x;
    if (i >= BNK_) return;
    int bn = i >> 9, k = i & (K_ - 1);
    const float* pp = phi + bn * 3;
    const float* z = g_Z + (long long)bn * KG_;
    float c = sign * (pp[0] * z[k] + pp[1] * z[K_ + k] + pp[2] * z[2 * K_ + k]);
    float r = xbase[i] + g_a1[i] + 0.5f * c;
    if (resid) r += resid[i];
    outp[i] = r;
}

// ---------------- fused attention prep + per-head gamma/delta reductions ----------------
__global__ void prep_attn_gamdel_kernel()
{
    int bn = blockIdx.x;                 // b*N + n
    int b = bn >> 10, n = bn & (N_ - 1);
    int t = threadIdx.x;
    int lane = t & 31;
    __shared__ float sacc[3][H_];
    if (t < 3 * H_) ((float*)sacc)[t] = 0.f;
    __syncthreads();

#pragma unroll
    for (int half = 0; half < 2; half++) {
        int k = t + half * 256;
        long long s2b = (long long)bn * (2 * K_);
        long long qb  = (long long)bn * QKVW_;
        long long ib  = (long long)bn * K_ + k;
        float sqraw = g_s2[s2b + k] + 1e-8f;
        float inv = 1.f / sqraw;
        float q = g_qkv[qb + k];
        g_inv[ib]  = inv;
        g_qinv[ib] = q * inv;
        float sk = g_s2[s2b + K_ + k] + 1e-8f;
        float kv = g_qkv[qb + K_ + k];
        g_e[ib] = sk + kv * kv;

        float qq  = q * q * inv;
        float lsq = logf(sqraw);
        float lsk = logf(sk);
        qq = warpSum(qq); lsq = warpSum(lsq); lsk = warpSum(lsk);
        if (lane == 0) {
            int h = k >> 6;
            atomicAdd(&sacc[0][h], qq);
            atomicAdd(&sacc[1][h], lsq);
            atomicAdd(&sacc[2][h], lsk);
        }
    }
    __syncthreads();
    if (t < H_) {
        int idx = ((b * H_ + t) * N_) + n;
        g_gam[idx] = -0.5f * (sacc[0][t] - (float)DH_ + sacc[1][t]);
        g_del[idx] = 0.5f * sacc[2][t];
    }
}

// ---------------- KL score kernel: tf32 mma, 64x64 tiles ----------------
__global__ __launch_bounds__(256) void score_kernel()
{
    int bh = blockIdx.z;
    int b = bh >> 3, h = bh & 7;
    int i0 = blockIdx.y * 64, j0 = blockIdx.x * 64;
    if (j0 > i0) return;               // fully masked tile: never read downstream

    constexpr int LDK = 68;
    __shared__ float Qs[64 * LDK];
    __shared__ float Ks[64 * LDK];
    int tid = threadIdx.x;
    int wid = tid >> 5, lane = tid & 31;
    int wm = wid & 3, wn = wid >> 2;
    int lr = lane >> 2, lc = lane & 3;
    int hoff = h * DH_;

    float acc[4][4] = {};

#pragma unroll
    for (int dc = 0; dc < 2; dc++) {
        for (int e = tid; e < 64 * 16; e += 256) {
            int r = e >> 4, c4 = (e & 15) * 4;
            long long qrow = (long long)(b * N_ + i0 + r);
            long long krow = (long long)(b * N_ + j0 + r);
            float4 qv, kv;
            if (dc == 0) {
                qv = *(const float4*)&g_inv[qrow * K_ + hoff + c4];
                qv.x *= -0.5f; qv.y *= -0.5f; qv.z *= -0.5f; qv.w *= -0.5f;
                kv = *(const float4*)&g_e[krow * K_ + hoff + c4];
            } else {
                qv = *(const float4*)&g_qinv[qrow * K_ + hoff + c4];
                kv = *(const float4*)&g_qkv[krow * QKVW_ + K_ + hoff + c4];
            }
            *(float4*)&Qs[r * LDK + c4] = qv;
            *(float4*)&Ks[r * LDK + c4] = kv;
        }
        __syncthreads();
#pragma unroll
        for (int ks = 0; ks < 8; ks++) {
            int kb = ks * 8 + lc;
            int ar = wm * 16 + lr;
            unsigned a0 = f2tf(Qs[ar * LDK + kb]);
            unsigned a1 = f2tf(Qs[(ar + 8) * LDK + kb]);
            unsigned a2 = f2tf(Qs[ar * LDK + kb + 4]);
            unsigned a3 = f2tf(Qs[(ar + 8) * LDK + kb + 4]);
#pragma unroll
            for (int ni = 0; ni < 4; ni++) {
                int bc = wn * 32 + ni * 8 + lr;
                unsigned b0 = f2tf(Ks[bc * LDK + kb]);
                unsigned b1 = f2tf(Ks[bc * LDK + kb + 4]);
                asm volatile(
                    "mma.sync.aligned.m16n8k8.row.col.f32.tf32.tf32.f32 "
                    "{%0,%1,%2,%3}, {%4,%5,%6,%7}, {%8,%9}, {%0,%1,%2,%3};"
                    : "+f"(acc[ni][0]), "+f"(acc[ni][1]),
                      "+f"(acc[ni][2]), "+f"(acc[ni][3])
                    : "r"(a0), "r"(a1), "r"(a2), "r"(a3), "r"(b0), "r"(b1));
            }
        }
        __syncthreads();
    }

    long long gdb = (long long)bh * N_;
#pragma unroll
    for (int half = 0; half < 2; half++) {
        int i = i0 + wm * 16 + lr + half * 8;
        float gv = g_gam[gdb + i];
#pragma unroll
        for (int ni = 0; ni < 4; ni++) {
            int j = j0 + wn * 32 + ni * 8 + 2 * lc;
            float2 o;
            o.x = acc[ni][half * 2 + 0] + gv + g_del[gdb + j];
            o.y = acc[ni][half * 2 + 1] + gv + g_del[gdb + j + 1];
            *(float2*)&g_beta[(gdb + i) * N_ + j] = o;
        }
    }
}

// ---------------- fused softmax (8 heads) + beta_m head-mean, causal-truncated ----------------
__global__ __launch_bounds__(256) void softmax_bm_kernel()
{
    int bi = blockIdx.x;               // b*N + i
    int b = bi >> 10, i = bi & (N_ - 1);
    int Jmax = ((i >> 7) + 1) << 7;
    int t = threadIdx.x;
    int lane = t & 31, w = t >> 5;
    __shared__ float red[8];
    __shared__ float s_val;
    float bmacc[4] = {0.f, 0.f, 0.f, 0.f};

    for (int h = 0; h < H_; h++) {
        float* p = g_beta + (((long long)(b * H_ + h)) * N_ + i) * N_;
        float ev[4];
        float m = -1e30f;
#pragma unroll
        for (int jj = 0; jj < 4; jj++) {
            int j = t + jj * 256;
            ev[jj] = (j <= i) ? p[j] : -1e30f;
            m = fmaxf(m, ev[jj]);
        }
        m = warpMax(m);
        if (lane == 0) red[w] = m;
        __syncthreads();
        if (t == 0) {
            float mm = red[0];
            for (int x = 1; x < 8; x++) mm = fmaxf(mm, red[x]);
            s_val = mm;
        }
        __syncthreads();
        m = s_val;
        float s = 0.f;
#pragma unroll
        for (int jj = 0; jj < 4; jj++) {
            ev[jj] = (t + jj * 256 <= i) ? expf(ev[jj] - m) : 0.f;
            s += ev[jj];
        }
        s = warpSum(s);
        if (lane == 0) red[w] = s;
        __syncthreads();
        if (t == 0) {
            float tot = 0.f;
            for (int x = 0; x < 8; x++) tot += red[x];
            s_val = 1.f / tot;
        }
        __syncthreads();
        float inv = s_val;
#pragma unroll
        for (int jj = 0; jj < 4; jj++) {
            int j = t + jj * 256;
            float v = ev[jj] * inv;
            if (j < Jmax) p[j] = v;
            bmacc[jj] += v;
        }
        __syncthreads();
    }

    float* bm = g_bm + ((long long)b * N_ + i) * N_;
#pragma unroll
    for (int jj = 0; jj < 4; jj++) {
        int j = t + jj * 256;
        if (j < Jmax) bm[j] = bmacc[jj] * 0.125f;
    }
}

// ---------------- host ----------------
static inline void launch_gemm(const float* A, const float* B, float* C,
                               int M, int N, int Kd, int lda, int ldb, int ldc,
                               long long sAo, long long sAi, long long sBo, long long sBi,
                               long long sCo, long long sCi, int innerDiv, int batch,
                               int causal = 0, int epi = 0,
                               const float* bias = nullptr,
                               const float* e_hin = nullptr, const float* e_prior = nullptr,
                               const float* e_aux = nullptr, const float* e_lr = nullptr,
                               const float* e_res = nullptr, const float* e_ln2 = nullptr)
{
    if (N % 128 == 0) {
        constexpr int SM = 3 * (128 * 20 + 16 * 136) * 4;   // 56832
        dim3 g(N / 128, M / 128, batch);
        gemm_tf32<128, 64, 8><<<g, 256, SM>>>(A, B, C, M, N, Kd, lda, ldb, ldc,
                                              sAo, sAi, sBo, sBi, sCo, sCi, innerDiv, causal,
                                              epi, bias, e_hin, e_prior, e_aux, e_lr, e_res, e_ln2);
    } else {
        constexpr int SM = 3 * (128 * 20 + 16 * 72) * 4;    // 44544
        dim3 g(N / 64, M / 128, batch);
        gemm_tf32<64, 32, 4><<<g, 256, SM>>>(A, B, C, M, N, Kd, lda, ldb, ldc,
                                             sAo, sAi, sBo, sBi, sCo, sCi, innerDiv, causal,
                                             epi, bias, e_hin, e_prior, e_aux, e_lr, e_res, e_ln2);
    }
}

extern "C" void kernel_launch(void* const* d_in, const int* in_sizes, int n_in,
                              void* d_out, int out_size)
{
    const float* mu_q     = (const float*)d_in[0];
    const float* sigma_q  = (const float*)d_in[1];
    const float* phi      = (const float*)d_in[2];
    const float* gen      = (const float*)d_in[3];
    const float* mu_prior = (const float*)d_in[5];
    const float* Wq  = (const float*)d_in[6];
    const float* Wk  = (const float*)d_in[7];
    const float* Wv  = (const float*)d_in[8];
    const float* Wo  = (const float*)d_in[9];
    const float* g1  = (const float*)d_in[10];
    const float* be1 = (const float*)d_in[11];
    const float* g2  = (const float*)d_in[12];
    const float* be2 = (const float*)d_in[13];
    const float* W1  = (const float*)d_in[14];
    const float* bh1 = (const float*)d_in[15];
    const float* W2  = (const float*)d_in[16];
    const float* bh2 = (const float*)d_in[17];
    const float* lr  = (const float*)d_in[18];

    static int attrDone = 0;
    if (!attrDone) {
        cudaFuncSetAttribute(gemm_tf32<128, 64, 8>,
                             cudaFuncAttributeMaxDynamicSharedMemorySize, 57344);
        cudaFuncSetAttribute(gemm_tf32<64, 32, 4>,
                             cudaFuncAttributeMaxDynamicSharedMemorySize, 45056);
        attrDone = 1;
    }

    void* tp;
#define GETSYM(var, sym) cudaGetSymbolAddress(&tp, sym); float* var = (float*)tp
    GETSYM(p_gcat, g_gcat);  GETSYM(p_wqkv, g_wqkv); GETSYM(p_w2qk, g_w2qk);
    GETSYM(p_ln1, g_ln1);    GETSYM(p_Z, g_Z);       GETSYM(p_a1, g_a1);
    GETSYM(p_mug, g_mug);    GETSYM(p_qkv, g_qkv);   GETSYM(p_s2, g_s2);
    GETSYM(p_beta, g_beta);  GETSYM(p_bm, g_bm);     GETSYM(p_attn, g_attn);
    GETSYM(p_o, g_o);        GETSYM(p_res, g_res);   GETSYM(p_ln2, g_ln2);
    GETSYM(p_h, g_h);        GETSYM(p_hid, g_hid);   GETSYM(p_bh, g_bh);
#undef GETSYM

    const int EW = 256;
    const int GB_BNK = BNK_ / EW;

    prep_gcat_kernel<<<(K_ * KG_ + EW - 1) / EW, EW>>>(gen);
    prep_wqkv_kernel<<<(K_ * QKVW_ + EW - 1) / EW, EW>>>(Wq, Wk, Wv);
    prep_w2qk_kernel<<<(K_ * 2 * K_ + EW - 1) / EW, EW>>>(Wq, Wk);

    // ---- attention sublayer ----
    ln_kernel<<<BN_, 256>>>(mu_q, g1, be1, p_ln1);

    launch_gemm(p_ln1, p_gcat, p_Z, BN_, KG_, K_, K_, KG_, KG_, 0,0,0,0,0,0, 1, 1);
    combine1_kernel<<<GB_BNK, EW>>>(phi, 1.f);
    launch_gemm(p_a1, p_gcat, p_Z, BN_, KG_, K_, K_, KG_, KG_, 0,0,0,0,0,0, 1, 1);
    combine2_kernel<<<GB_BNK, EW>>>(phi, 1.f, p_ln1, nullptr, p_mug);

    launch_gemm(p_mug, p_wqkv, p_qkv, BN_, QKVW_, K_, K_, QKVW_, QKVW_, 0,0,0,0,0,0, 1, 1);
    launch_gemm(sigma_q, p_w2qk, p_s2, BN_, 2 * K_, K_, K_, 2 * K_, 2 * K_, 0,0,0,0,0,0, 1, 1);

    prep_attn_gamdel_kernel<<<BN_, 256>>>();

    score_kernel<<<dim3(N_ / 64, N_ / 64, B_ * H_), 256>>>();
    softmax_bm_kernel<<<BN_, 256>>>();

    // out = beta @ v  (batched over b,h), causal K-truncation
    launch_gemm(p_beta, p_qkv + 2 * K_, p_attn, N_, DH_, N_, N_, QKVW_, K_,
                8LL * NN_, (long long)NN_,
                (long long)N_ * QKVW_, 64,
                (long long)N_ * K_, 64, H_, B_ * H_, 1);

    launch_gemm(p_attn, Wo, p_o, BN_, K_, K_, K_, K_, K_, 0,0,0,0,0,0, 1, 1);
    launch_gemm(p_o, p_gcat, p_Z, BN_, KG_, K_, K_, KG_, KG_, 0,0,0,0,0,0, 1, 1);
    combine1_kernel<<<GB_BNK, EW>>>(phi, -1.f);
    launch_gemm(p_a1, p_gcat, p_Z, BN_, KG_, K_, K_, KG_, KG_, 0,0,0,0,0,0, 1, 1);
    combine2_kernel<<<GB_BNK, EW>>>(phi, -1.f, p_o, mu_q, p_res);

    // ---- FFN sublayer ----
    ln_kernel<<<BN_, 256>>>(p_res, g2, be2, p_ln2);
    float* out = (float*)d_out;

    // iteration 1: h -> g_h
    launch_gemm(p_bm, p_ln2, p_bh, N_, K_, N_, N_, K_, K_,
                (long long)NN_, 0, (long long)N_ * K_, 0, (long long)N_ * K_, 0,
                1, B_, 1);
    launch_gemm(p_ln2, W1, p_hid, BN_, HID_, K_, K_, HID_, HID_, 0,0,0,0,0,0, 1, 1,
                0, 1, bh1);
    launch_gemm(p_hid, W2, p_h, BN_, K_, HID_, HID_, K_, K_, 0,0,0,0,0,0, 1, 1,
                0, 2, bh2, p_ln2, mu_prior, p_bh, lr);

    // iteration 2: final residual fused, writes directly to out
    launch_gemm(p_bm, p_h, p_bh, N_, K_, N_, N_, K_, K_,
                (long long)NN_, 0, (long long)N_ * K_, 0, (long long)N_ * K_, 0,
                1, B_, 1);
    launch_gemm(p_h, W1, p_hid, BN_, HID_, K_, K_, HID_, HID_, 0,0,0,0,0,0, 1, 1,
                0, 1, bh1);
    launch_gemm(p_hid, W2, out, BN_, K_, HID_, HID_, K_, K_, 0,0,0,0,0,0, 1, 1,
                0, 3, bh2, p_h, mu_prior, p_bh, lr, p_res, p_ln2);

    // ---- remaining outputs: (sigma_q, phi) ----
    cudaMemcpyAsync(out + BNK_, sigma_q, (size_t)BNK_ * sizeof(float),
                    cudaMemcpyDeviceToDevice);
    cudaMemcpyAsync(out + 2 * (size_t)BNK_, phi, (size_t)B_ * N_ * 3 * sizeof(float),
                    cudaMemcpyDeviceToDevice);
}